// round 4
// baseline (speedup 1.0000x reference)
#include <cuda_runtime.h>
#include <math.h>

// Problem constants
#define E_LAYERS 2
#define D_MODEL  512
#define D_STATE  16
#define DT_RANK  32
#define D_FF     2048
#define BATCH    16
#define SEQ      512
#define M_ROWS   (BATCH*SEQ)   // 8192

// -------------------- scratch (device globals; no allocation allowed) -----
__device__ float g_X   [M_ROWS * D_MODEL];
__device__ float g_XACC[M_ROWS * D_MODEL];
__device__ float g_XZ  [M_ROWS * 2 * D_MODEL];
__device__ float g_XC  [M_ROWS * D_MODEL];
__device__ float g_PROJ[M_ROWS * 64];
__device__ float g_DT  [M_ROWS * D_MODEL];
__device__ float g_Y   [M_ROWS * D_MODEL];
__device__ float g_FFNH[M_ROWS * D_FF];
__device__ float g_FFNO[M_ROWS * D_MODEL];

__device__ __forceinline__ int flip_row(int m) {
    return (m & ~(SEQ - 1)) + (SEQ - 1 - (m & (SEQ - 1)));
}

__device__ __forceinline__ float silu_f(float v) {
    return v / (1.f + expf(-v));
}

// -------------------- generic copy ---------------------------------------
__global__ void copy_k(float* __restrict__ dst, const float* __restrict__ src, int n) {
    int i = blockIdx.x * blockDim.x + threadIdx.x;
    if (i < n) dst[i] = src[i];
}

// -------------------- tiled SGEMM: C[m,n] = sum_k A[m,k] * W[n,k] ---------
// EPI: 0=none 1=gelu(exact) 2=softplus ; ACC: C += ; FLIPA/FLIPC: seq flip
template<int EPI, bool ACC, bool FLIPA, bool FLIPC>
__global__ void __launch_bounds__(256) gemm_k(
    const float* __restrict__ A, int lda,
    const float* __restrict__ W, int ldb,
    const float* __restrict__ bias,
    float* __restrict__ C, int ldc,
    int N, int K)
{
    __shared__ float As[8][128];
    __shared__ float Bs[8][128];

    const int tid = threadIdx.x;
    const int bm  = blockIdx.y * 128;
    const int bn  = blockIdx.x * 128;
    const int tr  = tid >> 4;   // 0..15
    const int tc  = tid & 15;   // 0..15

    float acc[8][8];
#pragma unroll
    for (int i = 0; i < 8; i++)
#pragma unroll
        for (int j = 0; j < 8; j++) acc[i][j] = 0.f;

    const int lr = tid >> 1;          // 0..127
    const int lk = (tid & 1) * 4;     // 0 or 4

    int am  = bm + lr;
    int ama = FLIPA ? flip_row(am) : am;
    const float* Aptr = A + (size_t)ama * lda + lk;

    int wn = bn + lr;
    bool wvalid = (wn < N);
    const float* Wptr = wvalid ? (W + (size_t)wn * ldb + lk) : W;

    for (int k0 = 0; k0 < K; k0 += 8) {
        float4 av = *(const float4*)(Aptr + k0);
        float4 wv = wvalid ? *(const float4*)(Wptr + k0) : make_float4(0.f,0.f,0.f,0.f);
        __syncthreads();
        As[lk+0][lr] = av.x; As[lk+1][lr] = av.y; As[lk+2][lr] = av.z; As[lk+3][lr] = av.w;
        Bs[lk+0][lr] = wv.x; Bs[lk+1][lr] = wv.y; Bs[lk+2][lr] = wv.z; Bs[lk+3][lr] = wv.w;
        __syncthreads();
#pragma unroll
        for (int k = 0; k < 8; k++) {
            float ar[8], br[8];
#pragma unroll
            for (int i = 0; i < 8; i++) ar[i] = As[k][tr*8 + i];
#pragma unroll
            for (int j = 0; j < 8; j++) br[j] = Bs[k][tc*8 + j];
#pragma unroll
            for (int i = 0; i < 8; i++)
#pragma unroll
                for (int j = 0; j < 8; j++)
                    acc[i][j] = fmaf(ar[i], br[j], acc[i][j]);
        }
    }

#pragma unroll
    for (int i = 0; i < 8; i++) {
        int cm  = bm + tr*8 + i;
        int cmm = FLIPC ? flip_row(cm) : cm;
        float* crow = C + (size_t)cmm * ldc;
#pragma unroll
        for (int j = 0; j < 8; j++) {
            int cn = bn + tc*8 + j;
            if (cn < N) {
                float v = acc[i][j];
                if (bias) v += bias[cn];
                if (EPI == 1) v = 0.5f * v * (1.f + erff(v * 0.70710678118654752f));
                if (EPI == 2) v = (v > 20.f) ? v : log1pf(expf(v));
                if (ACC) crow[cn] += v; else crow[cn] = v;
            }
        }
    }
}

// -------------------- causal depthwise conv (K=2) + SiLU ------------------
__global__ void conv_silu_k(const float* __restrict__ cw, const float* __restrict__ cb) {
    int i = blockIdx.x * blockDim.x + threadIdx.x;
    if (i >= M_ROWS * D_MODEL) return;
    int d   = i & (D_MODEL - 1);
    int row = i >> 9;
    int l   = row & (SEQ - 1);
    float xi   = g_XZ[(size_t)row * 1024 + d];
    float xim1 = (l > 0) ? g_XZ[(size_t)(row - 1) * 1024 + d] : 0.f;
    float v = cw[d*2 + 0] * xim1 + cw[d*2 + 1] * xi + cb[d];
    g_XC[i] = silu_f(v);
}

// -------------------- selective scan: 16 lanes = states per (b,d) ---------
__global__ void scan_k(const float* __restrict__ A_log, const float* __restrict__ D_skip) {
    int t = blockIdx.x * blockDim.x + threadIdx.x;   // 131072 threads
    int n = t & 15;
    int g = t >> 4;              // (b,d) group, 0..8191
    int b = g >> 9;
    int d = g & (D_MODEL - 1);

    float Aa  = -expf(A_log[d * D_STATE + n]);
    float Dsk = D_skip[d];
    float h = 0.f;
    size_t rbase = (size_t)b * SEQ;

    for (int l = 0; l < SEQ; l++) {
        size_t row = rbase + l;
        float dtv = g_DT[row * D_MODEL + d];
        float xcv = g_XC[row * D_MODEL + d];
        float Bv  = g_PROJ[row * 64 + 32 + n];
        float Cv  = g_PROJ[row * 64 + 48 + n];
        h = expf(dtv * Aa) * h + dtv * Bv * xcv;
        float p = h * Cv;
        p += __shfl_xor_sync(0xffffffffu, p, 8, 16);
        p += __shfl_xor_sync(0xffffffffu, p, 4, 16);
        p += __shfl_xor_sync(0xffffffffu, p, 2, 16);
        p += __shfl_xor_sync(0xffffffffu, p, 1, 16);
        if (n == 0) {
            float z = g_XZ[row * 1024 + 512 + d];
            float y = p + Dsk * xcv;
            g_Y[row * D_MODEL + d] = y * silu_f(z);
        }
    }
}

// -------------------- layernorm (optional residual add) -------------------
__global__ void ln_k(const float* __restrict__ in, const float* __restrict__ res,
                     const float* __restrict__ w, const float* __restrict__ b,
                     float* __restrict__ out)
{
    int row = blockIdx.x;
    int tid = threadIdx.x;     // 128 threads, 4 elems each
    float v[4];
    float s = 0.f, q = 0.f;
#pragma unroll
    for (int i = 0; i < 4; i++) {
        int c = tid + i * 128;
        float x = in[(size_t)row * D_MODEL + c];
        if (res) x += res[(size_t)row * D_MODEL + c];
        v[i] = x;
        s += x; q += x * x;
    }
    __shared__ float shs[4], shq[4];
#pragma unroll
    for (int off = 16; off; off >>= 1) {
        s += __shfl_xor_sync(0xffffffffu, s, off);
        q += __shfl_xor_sync(0xffffffffu, q, off);
    }
    if ((tid & 31) == 0) { shs[tid >> 5] = s; shq[tid >> 5] = q; }
    __syncthreads();
    if (tid == 0) {
        float ts = shs[0] + shs[1] + shs[2] + shs[3];
        float tq = shq[0] + shq[1] + shq[2] + shq[3];
        shs[0] = ts; shq[0] = tq;
    }
    __syncthreads();
    float m   = shs[0] * (1.f / D_MODEL);
    float var = shq[0] * (1.f / D_MODEL) - m * m;
    float inv = rsqrtf(var + 1e-5f);
#pragma unroll
    for (int i = 0; i < 4; i++) {
        int c = tid + i * 128;
        out[(size_t)row * D_MODEL + c] = (v[i] - m) * inv * w[c] + b[c];
    }
}

// ==========================================================================
extern "C" void kernel_launch(void* const* d_in, const int* in_sizes, int n_in,
                              void* d_out, int out_size)
{
    const float* x_in    = (const float*)d_in[0];
    const float* in_w    = (const float*)d_in[1];   // [2,2,1024,512]
    const float* conv_w  = (const float*)d_in[2];   // [2,2,512,2]
    const float* conv_b  = (const float*)d_in[3];   // [2,2,512]
    const float* xproj_w = (const float*)d_in[4];   // [2,2,64,512]
    const float* dt_w    = (const float*)d_in[5];   // [2,2,512,32]
    const float* dt_b    = (const float*)d_in[6];   // [2,2,512]
    const float* A_log   = (const float*)d_in[7];   // [2,2,512,16]
    const float* D_skip  = (const float*)d_in[8];   // [2,2,512]
    const float* out_w   = (const float*)d_in[9];   // [2,2,512,512]
    const float* ffn1_w  = (const float*)d_in[10];  // [2,2048,512]
    const float* ffn1_b  = (const float*)d_in[11];  // [2,2048]
    const float* ffn2_w  = (const float*)d_in[12];  // [2,512,2048]
    const float* ffn2_b  = (const float*)d_in[13];  // [2,512]
    const float* n1_w    = (const float*)d_in[14];
    const float* n1_b    = (const float*)d_in[15];
    const float* n2_w    = (const float*)d_in[16];
    const float* n2_b    = (const float*)d_in[17];
    const float* fn_w    = (const float*)d_in[18];
    const float* fn_b    = (const float*)d_in[19];

    float *X, *XACC, *XZ, *XC, *PROJ, *DT, *Y, *FFNH, *FFNO;
    cudaGetSymbolAddress((void**)&X,    g_X);
    cudaGetSymbolAddress((void**)&XACC, g_XACC);
    cudaGetSymbolAddress((void**)&XZ,   g_XZ);
    cudaGetSymbolAddress((void**)&XC,   g_XC);
    cudaGetSymbolAddress((void**)&PROJ, g_PROJ);
    cudaGetSymbolAddress((void**)&DT,   g_DT);
    cudaGetSymbolAddress((void**)&Y,    g_Y);
    cudaGetSymbolAddress((void**)&FFNH, g_FFNH);
    cudaGetSymbolAddress((void**)&FFNO, g_FFNO);

    const int NELEM = M_ROWS * D_MODEL;              // 4194304
    const int cgrid = (NELEM + 255) / 256;

    // X = input x
    copy_k<<<cgrid, 256>>>(X, x_in, NELEM);

    for (int e = 0; e < E_LAYERS; e++) {
        // XACC = X (residual accumulator for x + fwd + flip(rev))
        copy_k<<<cgrid, 256>>>(XACC, X, NELEM);

        for (int dir = 0; dir < 2; dir++) {
            int s = e * 2 + dir;
            const float* inw  = in_w    + (size_t)s * 1024 * 512;
            const float* cw   = conv_w  + (size_t)s * 512 * 2;
            const float* cb   = conv_b  + (size_t)s * 512;
            const float* xpw  = xproj_w + (size_t)s * 64 * 512;
            const float* dtw  = dt_w    + (size_t)s * 512 * 32;
            const float* dtb  = dt_b    + (size_t)s * 512;
            const float* alog = A_log   + (size_t)s * 512 * 16;
            const float* dsk  = D_skip  + (size_t)s * 512;
            const float* ow   = out_w   + (size_t)s * 512 * 512;

            // 1) xz = x @ in_w^T  (rev: read x at flipped rows)
            {
                dim3 g(1024/128, M_ROWS/128);
                if (dir == 0)
                    gemm_k<0,false,false,false><<<g,256>>>(X,512, inw,512, nullptr, XZ,1024, 1024,512);
                else
                    gemm_k<0,false,true ,false><<<g,256>>>(X,512, inw,512, nullptr, XZ,1024, 1024,512);
            }
            // 2) causal depthwise conv + silu -> XC
            conv_silu_k<<<cgrid, 256>>>(cw, cb);
            // 3) proj = xc @ xproj^T  (N=64)
            {
                dim3 g(1, M_ROWS/128);
                gemm_k<0,false,false,false><<<g,256>>>(XC,512, xpw,512, nullptr, PROJ,64, 64,512);
            }
            // 4) dt = softplus(proj[:, :32] @ dt_w^T + dt_b)
            {
                dim3 g(512/128, M_ROWS/128);
                gemm_k<2,false,false,false><<<g,256>>>(PROJ,64, dtw,32, dtb, DT,512, 512,32);
            }
            // 5) selective scan -> Y (gated with silu(z))
            scan_k<<<(M_ROWS*16)/256, 256>>>(alog, dsk);
            // 6) XACC += Y @ out_w^T  (rev: write at flipped rows)
            {
                dim3 g(512/128, M_ROWS/128);
                if (dir == 0)
                    gemm_k<0,true,false,false><<<g,256>>>(Y,512, ow,512, nullptr, XACC,512, 512,512);
                else
                    gemm_k<0,true,false,true ><<<g,256>>>(Y,512, ow,512, nullptr, XACC,512, 512,512);
            }
        }

        // x = LN1(XACC)
        ln_k<<<M_ROWS, 128>>>(XACC, nullptr, n1_w + e*512, n1_b + e*512, X);

        // FFN: h = gelu(x @ W1^T + b1); y = h @ W2^T + b2
        {
            dim3 g1(D_FF/128, M_ROWS/128);
            gemm_k<1,false,false,false><<<g1,256>>>(X,512, ffn1_w + (size_t)e*D_FF*512, 512,
                                                    ffn1_b + e*D_FF, FFNH, D_FF, D_FF, 512);
            dim3 g2(512/128, M_ROWS/128);
            gemm_k<0,false,false,false><<<g2,256>>>(FFNH, D_FF, ffn2_w + (size_t)e*512*D_FF, D_FF,
                                                    ffn2_b + e*512, FFNO, 512, 512, D_FF);
        }
        // x = LN2(x + y)
        ln_k<<<M_ROWS, 128>>>(X, FFNO, n2_w + e*512, n2_b + e*512, X);
    }

    // final LN -> d_out
    ln_k<<<M_ROWS, 128>>>(X, nullptr, fn_w, fn_b, (float*)d_out);
}

// round 13
// speedup vs baseline: 1.3064x; 1.3064x over previous
#include <cuda_runtime.h>
#include <cuda_bf16.h>
#include <math.h>
#include <stdint.h>

// Problem constants
#define E_LAYERS 2
#define D_MODEL  512
#define D_STATE  16
#define DT_RANK  32
#define D_FF     2048
#define BATCH    16
#define SEQ      512
#define M_ROWS   (BATCH*SEQ)   // 8192

// -------------------- scratch (device globals; no allocation allowed) -----
__device__ float g_X   [M_ROWS * D_MODEL];
__device__ float g_XACC[M_ROWS * D_MODEL];
__device__ float g_XZ  [M_ROWS * 2 * D_MODEL];
__device__ float g_XC  [M_ROWS * D_MODEL];
__device__ float g_PROJ[M_ROWS * 64];
__device__ float g_DT  [M_ROWS * D_MODEL];
__device__ float g_Y   [M_ROWS * D_MODEL];
__device__ float g_FFNH[M_ROWS * D_FF];
__device__ float g_FFNO[M_ROWS * D_MODEL];

__device__ __forceinline__ int flip_row(int m) {
    return (m & ~(SEQ - 1)) + (SEQ - 1 - (m & (SEQ - 1)));
}
__device__ __forceinline__ float silu_f(float v) { return v / (1.f + expf(-v)); }

// -------------------- generic copy ---------------------------------------
__global__ void copy_k(float* __restrict__ dst, const float* __restrict__ src, int n) {
    int i = blockIdx.x * blockDim.x + threadIdx.x;
    if (i < n) dst[i] = src[i];
}

// ==================== bf16x3 tensor-core GEMM (mma.sync) ==================
// C[m,n] = sum_k A[m,k] * W[n,k].  A:[M,K] row-major, W:[N,K] row-major.
// fp32 emulated via bf16 hi/lo split: Ah*Bh + Ah*Bl + Al*Bh (fp32 accum).
// CTA tile 128x64, BK=32, 8 warps (4x2), warp tile 32x32 (m16n8k16 frags).
// EPI: 0=none 1=gelu(exact). ACC: C+=. FLIPA/FLIPC: seq-flip row on read/write.
#define BM   128
#define BN   64
#define BK   32
#define PADK 40   // bf16 elems per smem row (80B) -> conflict-light frag loads

__device__ __forceinline__ void mma_bf16(float c[4], uint32_t a0, uint32_t a1,
                                         uint32_t a2, uint32_t a3,
                                         uint32_t b0, uint32_t b1) {
    asm volatile(
        "mma.sync.aligned.m16n8k16.row.col.f32.bf16.bf16.f32 "
        "{%0,%1,%2,%3}, {%4,%5,%6,%7}, {%8,%9}, {%0,%1,%2,%3};"
        : "+f"(c[0]), "+f"(c[1]), "+f"(c[2]), "+f"(c[3])
        : "r"(a0), "r"(a1), "r"(a2), "r"(a3), "r"(b0), "r"(b1));
}

__device__ __forceinline__ void cvt_hl(float x, float y,
                                       __nv_bfloat162& h2, __nv_bfloat162& l2) {
    h2 = __floats2bfloat162_rn(x, y);
    l2 = __floats2bfloat162_rn(x - __bfloat162float(h2.x),
                               y - __bfloat162float(h2.y));
}

template<int EPI, bool ACC, bool FLIPA, bool FLIPC>
__global__ void __launch_bounds__(256, 2) mmagemm_k(
    const float* __restrict__ A, const float* __restrict__ W,
    const float* __restrict__ bias,
    float* __restrict__ C, int ldc, int K)
{
    __shared__ __nv_bfloat16 sAh[BM * PADK], sAl[BM * PADK];
    __shared__ __nv_bfloat16 sBh[BN * PADK], sBl[BN * PADK];

    const int tid  = threadIdx.x;
    const int lane = tid & 31;
    const int warp = tid >> 5;
    const int wm   = warp >> 1;          // 0..3  (4 x 32 rows = 128)
    const int wn   = warp & 1;           // 0..1  (2 x 32 cols = 64)
    const int lr   = lane >> 2;          // 0..7
    const int lc   = (lane & 3) * 2;     // 0,2,4,6
    const int bm   = blockIdx.y * BM;
    const int bn   = blockIdx.x * BN;

    // global loader mapping
    const int a_row = tid >> 1;                 // 0..127
    const int a_k0  = (tid & 1) * 16;           // 0 or 16
    const int b_row = tid >> 2;                 // 0..63
    const int b_k0  = (tid & 3) * 8;            // 0,8,16,24

    int arow_g = bm + a_row;
    if (FLIPA) arow_g = flip_row(arow_g);
    const float* aptr = A + (size_t)arow_g * K + a_k0;
    const float* bptr = W + (size_t)(bn + b_row) * K + b_k0;

    float acc[2][4][4];
#pragma unroll
    for (int mt = 0; mt < 2; mt++)
#pragma unroll
        for (int nt = 0; nt < 4; nt++)
#pragma unroll
            for (int r = 0; r < 4; r++) acc[mt][nt][r] = 0.f;

    const int NCH = K >> 5;   // K/32
    float4 pa[4], pb[2];
#pragma unroll
    for (int j = 0; j < 4; j++) pa[j] = *(const float4*)(aptr + j * 4);
#pragma unroll
    for (int j = 0; j < 2; j++) pb[j] = *(const float4*)(bptr + j * 4);

    for (int ch = 0; ch < NCH; ch++) {
        // convert staged registers -> smem (hi/lo bf16)
#pragma unroll
        for (int j = 0; j < 4; j++) {
            int k = a_k0 + j * 4;
            __nv_bfloat162 h2, l2;
            cvt_hl(pa[j].x, pa[j].y, h2, l2);
            *(__nv_bfloat162*)&sAh[a_row * PADK + k]     = h2;
            *(__nv_bfloat162*)&sAl[a_row * PADK + k]     = l2;
            cvt_hl(pa[j].z, pa[j].w, h2, l2);
            *(__nv_bfloat162*)&sAh[a_row * PADK + k + 2] = h2;
            *(__nv_bfloat162*)&sAl[a_row * PADK + k + 2] = l2;
        }
#pragma unroll
        for (int j = 0; j < 2; j++) {
            int k = b_k0 + j * 4;
            __nv_bfloat162 h2, l2;
            cvt_hl(pb[j].x, pb[j].y, h2, l2);
            *(__nv_bfloat162*)&sBh[b_row * PADK + k]     = h2;
            *(__nv_bfloat162*)&sBl[b_row * PADK + k]     = l2;
            cvt_hl(pb[j].z, pb[j].w, h2, l2);
            *(__nv_bfloat162*)&sBh[b_row * PADK + k + 2] = h2;
            *(__nv_bfloat162*)&sBl[b_row * PADK + k + 2] = l2;
        }
        __syncthreads();

        // prefetch next chunk while doing mma on this one
        if (ch + 1 < NCH) {
            const float* ap = aptr + (ch + 1) * 32;
            const float* bp = bptr + (ch + 1) * 32;
#pragma unroll
            for (int j = 0; j < 4; j++) pa[j] = *(const float4*)(ap + j * 4);
#pragma unroll
            for (int j = 0; j < 2; j++) pb[j] = *(const float4*)(bp + j * 4);
        }

#pragma unroll
        for (int kf = 0; kf < 2; kf++) {
            const int kb = kf * 16 + lc;
            uint32_t ah[2][4], al[2][4], bh[4][2], bl[4][2];
#pragma unroll
            for (int mt = 0; mt < 2; mt++) {
                int r0 = (wm * 32 + mt * 16 + lr) * PADK;
                int r8 = r0 + 8 * PADK;
                ah[mt][0] = *(const uint32_t*)&sAh[r0 + kb];
                ah[mt][1] = *(const uint32_t*)&sAh[r8 + kb];
                ah[mt][2] = *(const uint32_t*)&sAh[r0 + kb + 8];
                ah[mt][3] = *(const uint32_t*)&sAh[r8 + kb + 8];
                al[mt][0] = *(const uint32_t*)&sAl[r0 + kb];
                al[mt][1] = *(const uint32_t*)&sAl[r8 + kb];
                al[mt][2] = *(const uint32_t*)&sAl[r0 + kb + 8];
                al[mt][3] = *(const uint32_t*)&sAl[r8 + kb + 8];
            }
#pragma unroll
            for (int nt = 0; nt < 4; nt++) {
                int r = (wn * 32 + nt * 8 + lr) * PADK;
                bh[nt][0] = *(const uint32_t*)&sBh[r + kb];
                bh[nt][1] = *(const uint32_t*)&sBh[r + kb + 8];
                bl[nt][0] = *(const uint32_t*)&sBl[r + kb];
                bl[nt][1] = *(const uint32_t*)&sBl[r + kb + 8];
            }
#pragma unroll
            for (int mt = 0; mt < 2; mt++)
#pragma unroll
                for (int nt = 0; nt < 4; nt++) {
                    mma_bf16(acc[mt][nt], ah[mt][0], ah[mt][1], ah[mt][2], ah[mt][3],
                             bh[nt][0], bh[nt][1]);
                    mma_bf16(acc[mt][nt], ah[mt][0], ah[mt][1], ah[mt][2], ah[mt][3],
                             bl[nt][0], bl[nt][1]);
                    mma_bf16(acc[mt][nt], al[mt][0], al[mt][1], al[mt][2], al[mt][3],
                             bh[nt][0], bh[nt][1]);
                }
        }
        __syncthreads();
    }

    // epilogue
#pragma unroll
    for (int mt = 0; mt < 2; mt++) {
#pragma unroll
        for (int nt = 0; nt < 4; nt++) {
            int row0 = bm + wm * 32 + mt * 16 + lr;
            int row1 = row0 + 8;
            int col  = bn + wn * 32 + nt * 8 + lc;
            if (FLIPC) { row0 = flip_row(row0); row1 = flip_row(row1); }
            float2 v0 = make_float2(acc[mt][nt][0], acc[mt][nt][1]);
            float2 v1 = make_float2(acc[mt][nt][2], acc[mt][nt][3]);
            if (bias) {
                float b0 = bias[col], b1 = bias[col + 1];
                v0.x += b0; v0.y += b1; v1.x += b0; v1.y += b1;
            }
            if (EPI == 1) {
                v0.x = 0.5f * v0.x * (1.f + erff(v0.x * 0.70710678118654752f));
                v0.y = 0.5f * v0.y * (1.f + erff(v0.y * 0.70710678118654752f));
                v1.x = 0.5f * v1.x * (1.f + erff(v1.x * 0.70710678118654752f));
                v1.y = 0.5f * v1.y * (1.f + erff(v1.y * 0.70710678118654752f));
            }
            float* p0 = C + (size_t)row0 * ldc + col;
            float* p1 = C + (size_t)row1 * ldc + col;
            if (ACC) {
                float2 o0 = *(float2*)p0, o1 = *(float2*)p1;
                v0.x += o0.x; v0.y += o0.y; v1.x += o1.x; v1.y += o1.y;
            }
            *(float2*)p0 = v0;
            *(float2*)p1 = v1;
        }
    }
}

// -------------------- fp32 SGEMM (small shapes: xproj, dt) ----------------
// EPI: 0=none 2=softplus
template<int EPI>
__global__ void __launch_bounds__(256) gemm_k(
    const float* __restrict__ A, int lda,
    const float* __restrict__ W, int ldb,
    const float* __restrict__ bias,
    float* __restrict__ C, int ldc,
    int N, int K)
{
    __shared__ float As[8][128];
    __shared__ float Bs[8][128];

    const int tid = threadIdx.x;
    const int bm  = blockIdx.y * 128;
    const int bn  = blockIdx.x * 128;
    const int tr  = tid >> 4;
    const int tc  = tid & 15;

    float acc[8][8];
#pragma unroll
    for (int i = 0; i < 8; i++)
#pragma unroll
        for (int j = 0; j < 8; j++) acc[i][j] = 0.f;

    const int lr = tid >> 1;
    const int lk = (tid & 1) * 4;

    const float* Aptr = A + (size_t)(bm + lr) * lda + lk;
    int wn = bn + lr;
    bool wvalid = (wn < N);
    const float* Wptr = wvalid ? (W + (size_t)wn * ldb + lk) : W;

    for (int k0 = 0; k0 < K; k0 += 8) {
        float4 av = *(const float4*)(Aptr + k0);
        float4 wv = wvalid ? *(const float4*)(Wptr + k0) : make_float4(0.f, 0.f, 0.f, 0.f);
        __syncthreads();
        As[lk+0][lr] = av.x; As[lk+1][lr] = av.y; As[lk+2][lr] = av.z; As[lk+3][lr] = av.w;
        Bs[lk+0][lr] = wv.x; Bs[lk+1][lr] = wv.y; Bs[lk+2][lr] = wv.z; Bs[lk+3][lr] = wv.w;
        __syncthreads();
#pragma unroll
        for (int k = 0; k < 8; k++) {
            float ar[8], br[8];
#pragma unroll
            for (int i = 0; i < 8; i++) ar[i] = As[k][tr*8 + i];
#pragma unroll
            for (int j = 0; j < 8; j++) br[j] = Bs[k][tc*8 + j];
#pragma unroll
            for (int i = 0; i < 8; i++)
#pragma unroll
                for (int j = 0; j < 8; j++)
                    acc[i][j] = fmaf(ar[i], br[j], acc[i][j]);
        }
    }

#pragma unroll
    for (int i = 0; i < 8; i++) {
        float* crow = C + (size_t)(bm + tr*8 + i) * ldc;
#pragma unroll
        for (int j = 0; j < 8; j++) {
            int cn = bn + tc*8 + j;
            if (cn < N) {
                float v = acc[i][j];
                if (bias) v += bias[cn];
                if (EPI == 2) v = (v > 20.f) ? v : log1pf(expf(v));
                crow[cn] = v;
            }
        }
    }
}

// -------------------- causal depthwise conv (K=2) + SiLU ------------------
__global__ void conv_silu_k(const float* __restrict__ cw, const float* __restrict__ cb) {
    int i = blockIdx.x * blockDim.x + threadIdx.x;
    if (i >= M_ROWS * D_MODEL) return;
    int d   = i & (D_MODEL - 1);
    int row = i >> 9;
    int l   = row & (SEQ - 1);
    float xi   = g_XZ[(size_t)row * 1024 + d];
    float xim1 = (l > 0) ? g_XZ[(size_t)(row - 1) * 1024 + d] : 0.f;
    float v = cw[d*2 + 0] * xim1 + cw[d*2 + 1] * xi + cb[d];
    g_XC[i] = silu_f(v);
}

// -------------------- selective scan --------------------------------------
__global__ void scan_k(const float* __restrict__ A_log, const float* __restrict__ D_skip) {
    int t = blockIdx.x * blockDim.x + threadIdx.x;
    int n = t & 15;
    int g = t >> 4;
    int b = g >> 9;
    int d = g & (D_MODEL - 1);

    float Aa  = -expf(A_log[d * D_STATE + n]);
    float Dsk = D_skip[d];
    float h = 0.f;
    size_t rbase = (size_t)b * SEQ;

    for (int l = 0; l < SEQ; l++) {
        size_t row = rbase + l;
        float dtv = g_DT[row * D_MODEL + d];
        float xcv = g_XC[row * D_MODEL + d];
        float Bv  = g_PROJ[row * 64 + 32 + n];
        float Cv  = g_PROJ[row * 64 + 48 + n];
        h = expf(dtv * Aa) * h + dtv * Bv * xcv;
        float p = h * Cv;
        p += __shfl_xor_sync(0xffffffffu, p, 8, 16);
        p += __shfl_xor_sync(0xffffffffu, p, 4, 16);
        p += __shfl_xor_sync(0xffffffffu, p, 2, 16);
        p += __shfl_xor_sync(0xffffffffu, p, 1, 16);
        if (n == 0) {
            float z = g_XZ[row * 1024 + 512 + d];
            float y = p + Dsk * xcv;
            g_Y[row * D_MODEL + d] = y * silu_f(z);
        }
    }
}

// -------------------- layernorm (optional residual add) -------------------
__global__ void ln_k(const float* __restrict__ in, const float* __restrict__ res,
                     const float* __restrict__ w, const float* __restrict__ b,
                     float* __restrict__ out)
{
    int row = blockIdx.x;
    int tid = threadIdx.x;
    float v[4];
    float s = 0.f, q = 0.f;
#pragma unroll
    for (int i = 0; i < 4; i++) {
        int c = tid + i * 128;
        float x = in[(size_t)row * D_MODEL + c];
        if (res) x += res[(size_t)row * D_MODEL + c];
        v[i] = x;
        s += x; q += x * x;
    }
    __shared__ float shs[4], shq[4];
#pragma unroll
    for (int off = 16; off; off >>= 1) {
        s += __shfl_xor_sync(0xffffffffu, s, off);
        q += __shfl_xor_sync(0xffffffffu, q, off);
    }
    if ((tid & 31) == 0) { shs[tid >> 5] = s; shq[tid >> 5] = q; }
    __syncthreads();
    if (tid == 0) {
        shs[0] = shs[0] + shs[1] + shs[2] + shs[3];
        shq[0] = shq[0] + shq[1] + shq[2] + shq[3];
    }
    __syncthreads();
    float m   = shs[0] * (1.f / D_MODEL);
    float var = shq[0] * (1.f / D_MODEL) - m * m;
    float inv = rsqrtf(var + 1e-5f);
#pragma unroll
    for (int i = 0; i < 4; i++) {
        int c = tid + i * 128;
        out[(size_t)row * D_MODEL + c] = (v[i] - m) * inv * w[c] + b[c];
    }
}

// ==========================================================================
extern "C" void kernel_launch(void* const* d_in, const int* in_sizes, int n_in,
                              void* d_out, int out_size)
{
    const float* x_in    = (const float*)d_in[0];
    const float* in_w    = (const float*)d_in[1];
    const float* conv_w  = (const float*)d_in[2];
    const float* conv_b  = (const float*)d_in[3];
    const float* xproj_w = (const float*)d_in[4];
    const float* dt_w    = (const float*)d_in[5];
    const float* dt_b    = (const float*)d_in[6];
    const float* A_log   = (const float*)d_in[7];
    const float* D_skip  = (const float*)d_in[8];
    const float* out_w   = (const float*)d_in[9];
    const float* ffn1_w  = (const float*)d_in[10];
    const float* ffn1_b  = (const float*)d_in[11];
    const float* ffn2_w  = (const float*)d_in[12];
    const float* ffn2_b  = (const float*)d_in[13];
    const float* n1_w    = (const float*)d_in[14];
    const float* n1_b    = (const float*)d_in[15];
    const float* n2_w    = (const float*)d_in[16];
    const float* n2_b    = (const float*)d_in[17];
    const float* fn_w    = (const float*)d_in[18];
    const float* fn_b    = (const float*)d_in[19];

    float *X, *XACC, *XZ, *XC, *PROJ, *DT, *Y, *FFNH, *FFNO;
    cudaGetSymbolAddress((void**)&X,    g_X);
    cudaGetSymbolAddress((void**)&XACC, g_XACC);
    cudaGetSymbolAddress((void**)&XZ,   g_XZ);
    cudaGetSymbolAddress((void**)&XC,   g_XC);
    cudaGetSymbolAddress((void**)&PROJ, g_PROJ);
    cudaGetSymbolAddress((void**)&DT,   g_DT);
    cudaGetSymbolAddress((void**)&Y,    g_Y);
    cudaGetSymbolAddress((void**)&FFNH, g_FFNH);
    cudaGetSymbolAddress((void**)&FFNO, g_FFNO);

    const int NELEM = M_ROWS * D_MODEL;   // 4194304
    const int cgrid = (NELEM + 255) / 256;

    copy_k<<<cgrid, 256>>>(X, x_in, NELEM);

    for (int e = 0; e < E_LAYERS; e++) {
        copy_k<<<cgrid, 256>>>(XACC, X, NELEM);

        for (int dir = 0; dir < 2; dir++) {
            int s = e * 2 + dir;
            const float* inw  = in_w    + (size_t)s * 1024 * 512;
            const float* cw   = conv_w  + (size_t)s * 512 * 2;
            const float* cb   = conv_b  + (size_t)s * 512;
            const float* xpw  = xproj_w + (size_t)s * 64 * 512;
            const float* dtw  = dt_w    + (size_t)s * 512 * 32;
            const float* dtb  = dt_b    + (size_t)s * 512;
            const float* alog = A_log   + (size_t)s * 512 * 16;
            const float* dsk  = D_skip  + (size_t)s * 512;
            const float* ow   = out_w   + (size_t)s * 512 * 512;

            // 1) xz = x @ in_w^T (tensor cores; rev reads flipped rows)
            {
                dim3 g(1024 / BN, M_ROWS / BM);
                if (dir == 0)
                    mmagemm_k<0,false,false,false><<<g,256>>>(X, inw, nullptr, XZ, 1024, 512);
                else
                    mmagemm_k<0,false,true ,false><<<g,256>>>(X, inw, nullptr, XZ, 1024, 512);
            }
            // 2) conv + silu
            conv_silu_k<<<cgrid, 256>>>(cw, cb);
            // 3) proj = xc @ xproj^T (N=64, fp32 path)
            {
                dim3 g(1, M_ROWS / 128);
                gemm_k<0><<<g,256>>>(XC,512, xpw,512, nullptr, PROJ,64, 64,512);
            }
            // 4) dt = softplus(proj[:, :32] @ dt_w^T + dt_b)  (K=32, fp32 path)
            {
                dim3 g(512 / 128, M_ROWS / 128);
                gemm_k<2><<<g,256>>>(PROJ,64, dtw,32, dtb, DT,512, 512,32);
            }
            // 5) selective scan -> Y
            scan_k<<<(M_ROWS * 16) / 256, 256>>>(alog, dsk);
            // 6) XACC += Y @ out_w^T (tensor cores; rev writes flipped rows)
            {
                dim3 g(512 / BN, M_ROWS / BM);
                if (dir == 0)
                    mmagemm_k<0,true,false,false><<<g,256>>>(Y, ow, nullptr, XACC, 512, 512);
                else
                    mmagemm_k<0,true,false,true ><<<g,256>>>(Y, ow, nullptr, XACC, 512, 512);
            }
        }

        // LN1
        ln_k<<<M_ROWS, 128>>>(XACC, nullptr, n1_w + e*512, n1_b + e*512, X);

        // FFN1: h = gelu(x @ W1^T + b1)
        {
            dim3 g(D_FF / BN, M_ROWS / BM);
            mmagemm_k<1,false,false,false><<<g,256>>>(X, ffn1_w + (size_t)e*D_FF*512,
                                                      ffn1_b + e*D_FF, FFNH, D_FF, 512);
        }
        // FFN2: y = h @ W2^T + b2
        {
            dim3 g(512 / BN, M_ROWS / BM);
            mmagemm_k<0,false,false,false><<<g,256>>>(FFNH, ffn2_w + (size_t)e*512*D_FF,
                                                      ffn2_b + e*512, FFNO, 512, 2048);
        }
        // LN2
        ln_k<<<M_ROWS, 128>>>(X, FFNO, n2_w + e*512, n2_b + e*512, X);
    }

    ln_k<<<M_ROWS, 128>>>(X, nullptr, fn_w, fn_b, (float*)d_out);
}

// round 14
// speedup vs baseline: 1.4709x; 1.1260x over previous
#include <cuda_runtime.h>
#include <cuda_bf16.h>
#include <math.h>
#include <stdint.h>

// Problem constants
#define E_LAYERS 2
#define D_MODEL  512
#define D_STATE  16
#define DT_RANK  32
#define D_FF     2048
#define BATCH    16
#define SEQ      512
#define M_ROWS   (BATCH*SEQ)   // 8192

// -------------------- scratch (device globals; no allocation allowed) -----
__device__ float g_X   [M_ROWS * D_MODEL];
__device__ float g_XACC[M_ROWS * D_MODEL];
__device__ float g_XZ  [M_ROWS * 2 * D_MODEL];
__device__ float g_XC  [M_ROWS * D_MODEL];
__device__ float g_PROJ[M_ROWS * 64];
__device__ float g_DT  [M_ROWS * D_MODEL];
__device__ float g_Y   [M_ROWS * D_MODEL];
__device__ float g_FFNH[M_ROWS * D_FF];
__device__ float g_FFNO[M_ROWS * D_MODEL];

__device__ __forceinline__ int flip_row(int m) {
    return (m & ~(SEQ - 1)) + (SEQ - 1 - (m & (SEQ - 1)));
}
__device__ __forceinline__ float silu_f(float v) { return v / (1.f + expf(-v)); }

// -------------------- generic copy ---------------------------------------
__global__ void copy_k(float* __restrict__ dst, const float* __restrict__ src, int n) {
    int i = blockIdx.x * blockDim.x + threadIdx.x;
    if (i < n) dst[i] = src[i];
}

// ==================== bf16x3 tensor-core GEMM (mma.sync) ==================
// C[m,n] = sum_k A[m,k] * W[n,k].  A:[M,K] row-major, W:[N,K] row-major.
// fp32 emulated via bf16 hi/lo split: Ah*Bh + Ah*Bl + Al*Bh (fp32 accum).
// CTA tile 128x128, BK=32, 512 threads, 16 warps (4x4), warp tile 32x32.
// Double-buffered smem staging; one __syncthreads per K-chunk.
// EPI: 0=none 1=gelu(exact). ACC: C+=. FLIPA/FLIPC: seq-flip row on read/write.
#define BM   128
#define BN   128
#define BK   32
#define PADK 40                         // bf16 elems per smem row (80B)
#define STG_ELEMS (4 * 128 * PADK)      // AH,AL,BH,BL per stage = 20480 bf16
#define GEMM_SMEM (2 * STG_ELEMS * 2)   // 2 stages, bytes = 81920

__device__ __forceinline__ void mma_bf16(float c[4], uint32_t a0, uint32_t a1,
                                         uint32_t a2, uint32_t a3,
                                         uint32_t b0, uint32_t b1) {
    asm volatile(
        "mma.sync.aligned.m16n8k16.row.col.f32.bf16.bf16.f32 "
        "{%0,%1,%2,%3}, {%4,%5,%6,%7}, {%8,%9}, {%0,%1,%2,%3};"
        : "+f"(c[0]), "+f"(c[1]), "+f"(c[2]), "+f"(c[3])
        : "r"(a0), "r"(a1), "r"(a2), "r"(a3), "r"(b0), "r"(b1));
}

__device__ __forceinline__ void cvt_hl(float x, float y,
                                       __nv_bfloat162& h2, __nv_bfloat162& l2) {
    h2 = __floats2bfloat162_rn(x, y);
    l2 = __floats2bfloat162_rn(x - __bfloat162float(h2.x),
                               y - __bfloat162float(h2.y));
}

// store 8 floats (two float4) as hi/lo bf16 at [idx..idx+7]
__device__ __forceinline__ void st_hl8(__nv_bfloat16* hiB, __nv_bfloat16* loB,
                                       int idx, float4 v0, float4 v1) {
    __nv_bfloat162 h2, l2;
    cvt_hl(v0.x, v0.y, h2, l2);
    *(__nv_bfloat162*)&hiB[idx]     = h2;  *(__nv_bfloat162*)&loB[idx]     = l2;
    cvt_hl(v0.z, v0.w, h2, l2);
    *(__nv_bfloat162*)&hiB[idx + 2] = h2;  *(__nv_bfloat162*)&loB[idx + 2] = l2;
    cvt_hl(v1.x, v1.y, h2, l2);
    *(__nv_bfloat162*)&hiB[idx + 4] = h2;  *(__nv_bfloat162*)&loB[idx + 4] = l2;
    cvt_hl(v1.z, v1.w, h2, l2);
    *(__nv_bfloat162*)&hiB[idx + 6] = h2;  *(__nv_bfloat162*)&loB[idx + 6] = l2;
}

template<int EPI, bool ACC, bool FLIPA, bool FLIPC>
__global__ void __launch_bounds__(512, 1) mmagemm_k(
    const float* __restrict__ A, const float* __restrict__ W,
    const float* __restrict__ bias,
    float* __restrict__ C, int ldc, int K)
{
    extern __shared__ char smraw[];
    __nv_bfloat16* sm = (__nv_bfloat16*)smraw;

    const int tid  = threadIdx.x;
    const int lane = tid & 31;
    const int warp = tid >> 5;
    const int wm   = warp >> 2;          // 0..3  (4 x 32 rows = 128)
    const int wn   = warp & 3;           // 0..3  (4 x 32 cols = 128)
    const int lr   = lane >> 2;          // 0..7
    const int lc   = (lane & 3) * 2;     // 0,2,4,6
    const int bm   = blockIdx.y * BM;
    const int bn   = blockIdx.x * BN;

    // global loader mapping: 512 threads, each 8 floats of a 128x32 tile
    const int l_row = tid >> 2;          // 0..127
    const int l_k0  = (tid & 3) * 8;     // 0,8,16,24

    int arow_g = bm + l_row;
    if (FLIPA) arow_g = flip_row(arow_g);
    const float* aptr = A + (size_t)arow_g * K + l_k0;
    const float* bptr = W + (size_t)(bn + l_row) * K + l_k0;

    float acc[2][4][4];
#pragma unroll
    for (int mt = 0; mt < 2; mt++)
#pragma unroll
        for (int nt = 0; nt < 4; nt++)
#pragma unroll
            for (int r = 0; r < 4; r++) acc[mt][nt][r] = 0.f;

    const int NCH = K >> 5;
    float4 pa0, pa1, pb0, pb1;

    // prologue: load+stage chunk 0, preload chunk 1
    pa0 = *(const float4*)aptr;      pa1 = *(const float4*)(aptr + 4);
    pb0 = *(const float4*)bptr;      pb1 = *(const float4*)(bptr + 4);
    {
        __nv_bfloat16* st = sm;   // stage 0
        st_hl8(st,               st + STG_ELEMS/4*1, l_row * PADK + l_k0, pa0, pa1); // AH/AL
        st_hl8(st + STG_ELEMS/2, st + STG_ELEMS/4*3, l_row * PADK + l_k0, pb0, pb1); // BH/BL
    }
    if (NCH > 1) {
        pa0 = *(const float4*)(aptr + 32); pa1 = *(const float4*)(aptr + 36);
        pb0 = *(const float4*)(bptr + 32); pb1 = *(const float4*)(bptr + 36);
    }
    __syncthreads();

    for (int ch = 0; ch < NCH; ch++) {
        // stage chunk ch+1 into the other buffer; prefetch ch+2
        if (ch + 1 < NCH) {
            __nv_bfloat16* st = sm + ((ch + 1) & 1) * STG_ELEMS;
            st_hl8(st,               st + STG_ELEMS/4*1, l_row * PADK + l_k0, pa0, pa1);
            st_hl8(st + STG_ELEMS/2, st + STG_ELEMS/4*3, l_row * PADK + l_k0, pb0, pb1);
            if (ch + 2 < NCH) {
                const float* ap = aptr + (ch + 2) * 32;
                const float* bp = bptr + (ch + 2) * 32;
                pa0 = *(const float4*)ap; pa1 = *(const float4*)(ap + 4);
                pb0 = *(const float4*)bp; pb1 = *(const float4*)(bp + 4);
            }
        }

        // mma on stage ch&1
        const __nv_bfloat16* sAh = sm + (ch & 1) * STG_ELEMS;
        const __nv_bfloat16* sAl = sAh + STG_ELEMS/4;
        const __nv_bfloat16* sBh = sAh + STG_ELEMS/2;
        const __nv_bfloat16* sBl = sAh + STG_ELEMS/4*3;

#pragma unroll
        for (int kf = 0; kf < 2; kf++) {
            const int kb = kf * 16 + lc;
            uint32_t ah[2][4], al[2][4], bh[4][2], bl[4][2];
#pragma unroll
            for (int mt = 0; mt < 2; mt++) {
                int r0 = (wm * 32 + mt * 16 + lr) * PADK;
                int r8 = r0 + 8 * PADK;
                ah[mt][0] = *(const uint32_t*)&sAh[r0 + kb];
                ah[mt][1] = *(const uint32_t*)&sAh[r8 + kb];
                ah[mt][2] = *(const uint32_t*)&sAh[r0 + kb + 8];
                ah[mt][3] = *(const uint32_t*)&sAh[r8 + kb + 8];
                al[mt][0] = *(const uint32_t*)&sAl[r0 + kb];
                al[mt][1] = *(const uint32_t*)&sAl[r8 + kb];
                al[mt][2] = *(const uint32_t*)&sAl[r0 + kb + 8];
                al[mt][3] = *(const uint32_t*)&sAl[r8 + kb + 8];
            }
#pragma unroll
            for (int nt = 0; nt < 4; nt++) {
                int r = (wn * 32 + nt * 8 + lr) * PADK;
                bh[nt][0] = *(const uint32_t*)&sBh[r + kb];
                bh[nt][1] = *(const uint32_t*)&sBh[r + kb + 8];
                bl[nt][0] = *(const uint32_t*)&sBl[r + kb];
                bl[nt][1] = *(const uint32_t*)&sBl[r + kb + 8];
            }
#pragma unroll
            for (int mt = 0; mt < 2; mt++)
#pragma unroll
                for (int nt = 0; nt < 4; nt++) {
                    mma_bf16(acc[mt][nt], ah[mt][0], ah[mt][1], ah[mt][2], ah[mt][3],
                             bh[nt][0], bh[nt][1]);
                    mma_bf16(acc[mt][nt], ah[mt][0], ah[mt][1], ah[mt][2], ah[mt][3],
                             bl[nt][0], bl[nt][1]);
                    mma_bf16(acc[mt][nt], al[mt][0], al[mt][1], al[mt][2], al[mt][3],
                             bh[nt][0], bh[nt][1]);
                }
        }
        __syncthreads();
    }

    // epilogue
#pragma unroll
    for (int mt = 0; mt < 2; mt++) {
#pragma unroll
        for (int nt = 0; nt < 4; nt++) {
            int row0 = bm + wm * 32 + mt * 16 + lr;
            int row1 = row0 + 8;
            int col  = bn + wn * 32 + nt * 8 + lc;
            if (FLIPC) { row0 = flip_row(row0); row1 = flip_row(row1); }
            float2 v0 = make_float2(acc[mt][nt][0], acc[mt][nt][1]);
            float2 v1 = make_float2(acc[mt][nt][2], acc[mt][nt][3]);
            if (bias) {
                float b0 = bias[col], b1 = bias[col + 1];
                v0.x += b0; v0.y += b1; v1.x += b0; v1.y += b1;
            }
            if (EPI == 1) {
                v0.x = 0.5f * v0.x * (1.f + erff(v0.x * 0.70710678118654752f));
                v0.y = 0.5f * v0.y * (1.f + erff(v0.y * 0.70710678118654752f));
                v1.x = 0.5f * v1.x * (1.f + erff(v1.x * 0.70710678118654752f));
                v1.y = 0.5f * v1.y * (1.f + erff(v1.y * 0.70710678118654752f));
            }
            float* p0 = C + (size_t)row0 * ldc + col;
            float* p1 = C + (size_t)row1 * ldc + col;
            if (ACC) {
                float2 o0 = *(float2*)p0, o1 = *(float2*)p1;
                v0.x += o0.x; v0.y += o0.y; v1.x += o1.x; v1.y += o1.y;
            }
            *(float2*)p0 = v0;
            *(float2*)p1 = v1;
        }
    }
}

// -------------------- fp32 SGEMM (small shapes: xproj, dt) ----------------
// EPI: 0=none 2=softplus
template<int EPI>
__global__ void __launch_bounds__(256) gemm_k(
    const float* __restrict__ A, int lda,
    const float* __restrict__ W, int ldb,
    const float* __restrict__ bias,
    float* __restrict__ C, int ldc,
    int N, int K)
{
    __shared__ float As[8][128];
    __shared__ float Bs[8][128];

    const int tid = threadIdx.x;
    const int bm  = blockIdx.y * 128;
    const int bn  = blockIdx.x * 128;
    const int tr  = tid >> 4;
    const int tc  = tid & 15;

    float acc[8][8];
#pragma unroll
    for (int i = 0; i < 8; i++)
#pragma unroll
        for (int j = 0; j < 8; j++) acc[i][j] = 0.f;

    const int lr = tid >> 1;
    const int lk = (tid & 1) * 4;

    const float* Aptr = A + (size_t)(bm + lr) * lda + lk;
    int wn = bn + lr;
    bool wvalid = (wn < N);
    const float* Wptr = wvalid ? (W + (size_t)wn * ldb + lk) : W;

    for (int k0 = 0; k0 < K; k0 += 8) {
        float4 av = *(const float4*)(Aptr + k0);
        float4 wv = wvalid ? *(const float4*)(Wptr + k0) : make_float4(0.f, 0.f, 0.f, 0.f);
        __syncthreads();
        As[lk+0][lr] = av.x; As[lk+1][lr] = av.y; As[lk+2][lr] = av.z; As[lk+3][lr] = av.w;
        Bs[lk+0][lr] = wv.x; Bs[lk+1][lr] = wv.y; Bs[lk+2][lr] = wv.z; Bs[lk+3][lr] = wv.w;
        __syncthreads();
#pragma unroll
        for (int k = 0; k < 8; k++) {
            float ar[8], br[8];
#pragma unroll
            for (int i = 0; i < 8; i++) ar[i] = As[k][tr*8 + i];
#pragma unroll
            for (int j = 0; j < 8; j++) br[j] = Bs[k][tc*8 + j];
#pragma unroll
            for (int i = 0; i < 8; i++)
#pragma unroll
                for (int j = 0; j < 8; j++)
                    acc[i][j] = fmaf(ar[i], br[j], acc[i][j]);
        }
    }

#pragma unroll
    for (int i = 0; i < 8; i++) {
        float* crow = C + (size_t)(bm + tr*8 + i) * ldc;
#pragma unroll
        for (int j = 0; j < 8; j++) {
            int cn = bn + tc*8 + j;
            if (cn < N) {
                float v = acc[i][j];
                if (bias) v += bias[cn];
                if (EPI == 2) v = (v > 20.f) ? v : log1pf(expf(v));
                crow[cn] = v;
            }
        }
    }
}

// -------------------- causal depthwise conv (K=2) + SiLU ------------------
__global__ void conv_silu_k(const float* __restrict__ cw, const float* __restrict__ cb) {
    int i = blockIdx.x * blockDim.x + threadIdx.x;
    if (i >= M_ROWS * D_MODEL) return;
    int d   = i & (D_MODEL - 1);
    int row = i >> 9;
    int l   = row & (SEQ - 1);
    float xi   = g_XZ[(size_t)row * 1024 + d];
    float xim1 = (l > 0) ? g_XZ[(size_t)(row - 1) * 1024 + d] : 0.f;
    float v = cw[d*2 + 0] * xim1 + cw[d*2 + 1] * xi + cb[d];
    g_XC[i] = silu_f(v);
}

// -------------------- selective scan --------------------------------------
__global__ void scan_k(const float* __restrict__ A_log, const float* __restrict__ D_skip) {
    int t = blockIdx.x * blockDim.x + threadIdx.x;
    int n = t & 15;
    int g = t >> 4;
    int b = g >> 9;
    int d = g & (D_MODEL - 1);

    float Aa  = -expf(A_log[d * D_STATE + n]);
    float Dsk = D_skip[d];
    float h = 0.f;
    size_t rbase = (size_t)b * SEQ;

    for (int l = 0; l < SEQ; l++) {
        size_t row = rbase + l;
        float dtv = g_DT[row * D_MODEL + d];
        float xcv = g_XC[row * D_MODEL + d];
        float Bv  = g_PROJ[row * 64 + 32 + n];
        float Cv  = g_PROJ[row * 64 + 48 + n];
        h = expf(dtv * Aa) * h + dtv * Bv * xcv;
        float p = h * Cv;
        p += __shfl_xor_sync(0xffffffffu, p, 8, 16);
        p += __shfl_xor_sync(0xffffffffu, p, 4, 16);
        p += __shfl_xor_sync(0xffffffffu, p, 2, 16);
        p += __shfl_xor_sync(0xffffffffu, p, 1, 16);
        if (n == 0) {
            float z = g_XZ[row * 1024 + 512 + d];
            float y = p + Dsk * xcv;
            g_Y[row * D_MODEL + d] = y * silu_f(z);
        }
    }
}

// -------------------- layernorm (optional residual add) -------------------
__global__ void ln_k(const float* __restrict__ in, const float* __restrict__ res,
                     const float* __restrict__ w, const float* __restrict__ b,
                     float* __restrict__ out)
{
    int row = blockIdx.x;
    int tid = threadIdx.x;
    float v[4];
    float s = 0.f, q = 0.f;
#pragma unroll
    for (int i = 0; i < 4; i++) {
        int c = tid + i * 128;
        float x = in[(size_t)row * D_MODEL + c];
        if (res) x += res[(size_t)row * D_MODEL + c];
        v[i] = x;
        s += x; q += x * x;
    }
    __shared__ float shs[4], shq[4];
#pragma unroll
    for (int off = 16; off; off >>= 1) {
        s += __shfl_xor_sync(0xffffffffu, s, off);
        q += __shfl_xor_sync(0xffffffffu, q, off);
    }
    if ((tid & 31) == 0) { shs[tid >> 5] = s; shq[tid >> 5] = q; }
    __syncthreads();
    if (tid == 0) {
        shs[0] = shs[0] + shs[1] + shs[2] + shs[3];
        shq[0] = shq[0] + shq[1] + shq[2] + shq[3];
    }
    __syncthreads();
    float m   = shs[0] * (1.f / D_MODEL);
    float var = shq[0] * (1.f / D_MODEL) - m * m;
    float inv = rsqrtf(var + 1e-5f);
#pragma unroll
    for (int i = 0; i < 4; i++) {
        int c = tid + i * 128;
        out[(size_t)row * D_MODEL + c] = (v[i] - m) * inv * w[c] + b[c];
    }
}

// ==========================================================================
extern "C" void kernel_launch(void* const* d_in, const int* in_sizes, int n_in,
                              void* d_out, int out_size)
{
    const float* x_in    = (const float*)d_in[0];
    const float* in_w    = (const float*)d_in[1];
    const float* conv_w  = (const float*)d_in[2];
    const float* conv_b  = (const float*)d_in[3];
    const float* xproj_w = (const float*)d_in[4];
    const float* dt_w    = (const float*)d_in[5];
    const float* dt_b    = (const float*)d_in[6];
    const float* A_log   = (const float*)d_in[7];
    const float* D_skip  = (const float*)d_in[8];
    const float* out_w   = (const float*)d_in[9];
    const float* ffn1_w  = (const float*)d_in[10];
    const float* ffn1_b  = (const float*)d_in[11];
    const float* ffn2_w  = (const float*)d_in[12];
    const float* ffn2_b  = (const float*)d_in[13];
    const float* n1_w    = (const float*)d_in[14];
    const float* n1_b    = (const float*)d_in[15];
    const float* n2_w    = (const float*)d_in[16];
    const float* n2_b    = (const float*)d_in[17];
    const float* fn_w    = (const float*)d_in[18];
    const float* fn_b    = (const float*)d_in[19];

    float *X, *XACC, *XZ, *XC, *PROJ, *DT, *Y, *FFNH, *FFNO;
    cudaGetSymbolAddress((void**)&X,    g_X);
    cudaGetSymbolAddress((void**)&XACC, g_XACC);
    cudaGetSymbolAddress((void**)&XZ,   g_XZ);
    cudaGetSymbolAddress((void**)&XC,   g_XC);
    cudaGetSymbolAddress((void**)&PROJ, g_PROJ);
    cudaGetSymbolAddress((void**)&DT,   g_DT);
    cudaGetSymbolAddress((void**)&Y,    g_Y);
    cudaGetSymbolAddress((void**)&FFNH, g_FFNH);
    cudaGetSymbolAddress((void**)&FFNO, g_FFNO);

    // allow 80KB dynamic smem (idempotent host-side attribute, not a graph node)
    cudaFuncSetAttribute(mmagemm_k<0,false,false,false>, cudaFuncAttributeMaxDynamicSharedMemorySize, GEMM_SMEM);
    cudaFuncSetAttribute(mmagemm_k<0,false,true ,false>, cudaFuncAttributeMaxDynamicSharedMemorySize, GEMM_SMEM);
    cudaFuncSetAttribute(mmagemm_k<0,true ,false,false>, cudaFuncAttributeMaxDynamicSharedMemorySize, GEMM_SMEM);
    cudaFuncSetAttribute(mmagemm_k<0,true ,false,true >, cudaFuncAttributeMaxDynamicSharedMemorySize, GEMM_SMEM);
    cudaFuncSetAttribute(mmagemm_k<1,false,false,false>, cudaFuncAttributeMaxDynamicSharedMemorySize, GEMM_SMEM);

    const int NELEM = M_ROWS * D_MODEL;   // 4194304
    const int cgrid = (NELEM + 255) / 256;

    copy_k<<<cgrid, 256>>>(X, x_in, NELEM);

    for (int e = 0; e < E_LAYERS; e++) {
        copy_k<<<cgrid, 256>>>(XACC, X, NELEM);

        for (int dir = 0; dir < 2; dir++) {
            int s = e * 2 + dir;
            const float* inw  = in_w    + (size_t)s * 1024 * 512;
            const float* cw   = conv_w  + (size_t)s * 512 * 2;
            const float* cb   = conv_b  + (size_t)s * 512;
            const float* xpw  = xproj_w + (size_t)s * 64 * 512;
            const float* dtw  = dt_w    + (size_t)s * 512 * 32;
            const float* dtb  = dt_b    + (size_t)s * 512;
            const float* alog = A_log   + (size_t)s * 512 * 16;
            const float* dsk  = D_skip  + (size_t)s * 512;
            const float* ow   = out_w   + (size_t)s * 512 * 512;

            // 1) xz = x @ in_w^T (tensor cores; rev reads flipped rows)
            {
                dim3 g(1024 / BN, M_ROWS / BM);
                if (dir == 0)
                    mmagemm_k<0,false,false,false><<<g,512,GEMM_SMEM>>>(X, inw, nullptr, XZ, 1024, 512);
                else
                    mmagemm_k<0,false,true ,false><<<g,512,GEMM_SMEM>>>(X, inw, nullptr, XZ, 1024, 512);
            }
            // 2) conv + silu
            conv_silu_k<<<cgrid, 256>>>(cw, cb);
            // 3) proj = xc @ xproj^T (N=64, fp32 path)
            {
                dim3 g(1, M_ROWS / 128);
                gemm_k<0><<<g,256>>>(XC,512, xpw,512, nullptr, PROJ,64, 64,512);
            }
            // 4) dt = softplus(proj[:, :32] @ dt_w^T + dt_b)  (K=32, fp32 path)
            {
                dim3 g(512 / 128, M_ROWS / 128);
                gemm_k<2><<<g,256>>>(PROJ,64, dtw,32, dtb, DT,512, 512,32);
            }
            // 5) selective scan -> Y
            scan_k<<<(M_ROWS * 16) / 256, 256>>>(alog, dsk);
            // 6) XACC += Y @ out_w^T (tensor cores; rev writes flipped rows)
            {
                dim3 g(512 / BN, M_ROWS / BM);
                if (dir == 0)
                    mmagemm_k<0,true,false,false><<<g,512,GEMM_SMEM>>>(Y, ow, nullptr, XACC, 512, 512);
                else
                    mmagemm_k<0,true,false,true ><<<g,512,GEMM_SMEM>>>(Y, ow, nullptr, XACC, 512, 512);
            }
        }

        // LN1
        ln_k<<<M_ROWS, 128>>>(XACC, nullptr, n1_w + e*512, n1_b + e*512, X);

        // FFN1: h = gelu(x @ W1^T + b1)
        {
            dim3 g(D_FF / BN, M_ROWS / BM);
            mmagemm_k<1,false,false,false><<<g,512,GEMM_SMEM>>>(X, ffn1_w + (size_t)e*D_FF*512,
                                                                ffn1_b + e*D_FF, FFNH, D_FF, 512);
        }
        // FFN2: y = h @ W2^T + b2
        {
            dim3 g(512 / BN, M_ROWS / BM);
            mmagemm_k<0,false,false,false><<<g,512,GEMM_SMEM>>>(FFNH, ffn2_w + (size_t)e*512*D_FF,
                                                                ffn2_b + e*512, FFNO, 512, 2048);
        }
        // LN2
        ln_k<<<M_ROWS, 128>>>(X, FFNO, n2_w + e*512, n2_b + e*512, X);
    }

    ln_k<<<M_ROWS, 128>>>(X, nullptr, fn_w, fn_b, (float*)d_out);
}

// round 15
// speedup vs baseline: 1.5483x; 1.0526x over previous
#include <cuda_runtime.h>
#include <cuda_bf16.h>
#include <math.h>
#include <stdint.h>

// Problem constants
#define E_LAYERS 2
#define D_MODEL  512
#define D_STATE  16
#define DT_RANK  32
#define D_FF     2048
#define BATCH    16
#define SEQ      512
#define M_ROWS   (BATCH*SEQ)   // 8192

// -------------------- scratch (device globals; no allocation allowed) -----
__device__ float g_X   [M_ROWS * D_MODEL];
__device__ float g_XACC[M_ROWS * D_MODEL];
__device__ float g_XZ  [M_ROWS * 2 * D_MODEL];
__device__ float g_XC  [M_ROWS * D_MODEL];
__device__ float g_PROJ[M_ROWS * 64];
__device__ float g_DT  [M_ROWS * D_MODEL];
__device__ float g_Y   [M_ROWS * D_MODEL];
__device__ float g_FFNH[M_ROWS * D_FF];
__device__ float g_FFNO[M_ROWS * D_MODEL];
// bf16 hi/lo split operand buffers
__device__ __nv_bfloat16 g_Xhi[M_ROWS * D_MODEL];
__device__ __nv_bfloat16 g_Xlo[M_ROWS * D_MODEL];
__device__ __nv_bfloat16 g_Ahi[M_ROWS * D_FF];
__device__ __nv_bfloat16 g_Alo[M_ROWS * D_FF];
__device__ __nv_bfloat16 g_Whi[D_FF * D_MODEL];
__device__ __nv_bfloat16 g_Wlo[D_FF * D_MODEL];

__device__ __forceinline__ int flip_row(int m) {
    return (m & ~(SEQ - 1)) + (SEQ - 1 - (m & (SEQ - 1)));
}
__device__ __forceinline__ float silu_f(float v) { return v / (1.f + expf(-v)); }

__device__ __forceinline__ void cvt_hl(float x, float y,
                                       __nv_bfloat162& h2, __nv_bfloat162& l2) {
    h2 = __floats2bfloat162_rn(x, y);
    l2 = __floats2bfloat162_rn(x - __bfloat162float(h2.x),
                               y - __bfloat162float(h2.y));
}

// -------------------- generic copy ---------------------------------------
__global__ void copy_k(float* __restrict__ dst, const float* __restrict__ src, int n) {
    int i = blockIdx.x * blockDim.x + threadIdx.x;
    if (i < n) dst[i] = src[i];
}

// -------------------- fp32 -> bf16 hi/lo split -----------------------------
__global__ void split_bf16_k(const float* __restrict__ src,
                             __nv_bfloat16* __restrict__ hi,
                             __nv_bfloat16* __restrict__ lo, int n) {
    int i = (blockIdx.x * blockDim.x + threadIdx.x) * 4;
    if (i >= n) return;
    float4 v = *(const float4*)(src + i);
    __nv_bfloat162 h0, l0, h1, l1;
    cvt_hl(v.x, v.y, h0, l0);
    cvt_hl(v.z, v.w, h1, l1);
    *(__nv_bfloat162*)(hi + i)     = h0;
    *(__nv_bfloat162*)(hi + i + 2) = h1;
    *(__nv_bfloat162*)(lo + i)     = l0;
    *(__nv_bfloat162*)(lo + i + 2) = l1;
}

// ==================== bf16x3 tensor-core GEMM (mma.sync + ldmatrix) =======
// C[m,n] = sum_k A[m,k]*W[n,k]. Operands pre-split into bf16 hi/lo arrays.
// Emulated fp32: Ah*Bh + Ah*Bl + Al*Bh (fp32 accum).
// CTA tile 128x128, BK=32, 512 threads, 16 warps (4x4), warp tile 32x32.
// Double-buffered smem; fragments via ldmatrix.m8n8.x4 (PADK=40 -> no conflicts).
#define BM   128
#define BN   128
#define PADK 40                          // bf16 elems per smem row (80 B)
#define BLK_B  (128 * PADK * 2)          // one operand block bytes = 10240
#define STG_B  (4 * BLK_B)               // AH,AL,BH,BL per stage = 40960 B
#define GEMM_SMEM (2 * STG_B)            // 81920 B

__device__ __forceinline__ void mma_bf16(float c[4], uint32_t a0, uint32_t a1,
                                         uint32_t a2, uint32_t a3,
                                         uint32_t b0, uint32_t b1) {
    asm volatile(
        "mma.sync.aligned.m16n8k16.row.col.f32.bf16.bf16.f32 "
        "{%0,%1,%2,%3}, {%4,%5,%6,%7}, {%8,%9}, {%0,%1,%2,%3};"
        : "+f"(c[0]), "+f"(c[1]), "+f"(c[2]), "+f"(c[3])
        : "r"(a0), "r"(a1), "r"(a2), "r"(a3), "r"(b0), "r"(b1));
}

__device__ __forceinline__ void ldsm4(uint32_t& r0, uint32_t& r1,
                                      uint32_t& r2, uint32_t& r3, uint32_t addr) {
    asm volatile("ldmatrix.sync.aligned.m8n8.x4.shared.b16 {%0,%1,%2,%3}, [%4];"
                 : "=r"(r0), "=r"(r1), "=r"(r2), "=r"(r3) : "r"(addr));
}

template<int EPI, bool ACC, bool FLIPA, bool FLIPC>
__global__ void __launch_bounds__(512, 1) mmagemm_k(
    const __nv_bfloat16* __restrict__ Ahi, const __nv_bfloat16* __restrict__ Alo,
    const __nv_bfloat16* __restrict__ Whi, const __nv_bfloat16* __restrict__ Wlo,
    const float* __restrict__ bias,
    float* __restrict__ C, int ldc, int K)
{
    extern __shared__ char smraw[];

    const int tid  = threadIdx.x;
    const int lane = tid & 31;
    const int warp = tid >> 5;
    const int wm   = warp >> 2;          // 0..3
    const int wn   = warp & 3;           // 0..3
    const int lr   = lane >> 2;          // 0..7
    const int lc   = (lane & 3) * 2;     // 0,2,4,6
    const int bm   = blockIdx.y * BM;
    const int bn   = blockIdx.x * BN;

    // global loader: 512 threads, each 8 bf16 (16B) per operand per chunk
    const int l_row = tid >> 2;          // 0..127
    const int l_k0  = (tid & 3) * 8;     // 0,8,16,24

    int arow = bm + l_row;
    if (FLIPA) arow = flip_row(arow);
    const __nv_bfloat16* pAh = Ahi + (size_t)arow * K + l_k0;
    const __nv_bfloat16* pAl = Alo + (size_t)arow * K + l_k0;
    const __nv_bfloat16* pBh = Whi + (size_t)(bn + l_row) * K + l_k0;
    const __nv_bfloat16* pBl = Wlo + (size_t)(bn + l_row) * K + l_k0;

    const uint32_t smb    = (uint32_t)__cvta_generic_to_shared(smraw);
    const uint32_t stsoff = (uint32_t)(l_row * 80 + l_k0 * 2);
    // ldmatrix lane offsets (bytes within an operand block)
    const uint32_t a_l = (uint32_t)((wm * 32 + (lane & 15)) * 80 + ((lane >> 4) & 1) * 16);
    const uint32_t b_l = (uint32_t)((wn * 32 + (lane & 7) + ((lane >> 4) & 1) * 8) * 80
                                    + ((lane >> 3) & 1) * 16);

    float acc[2][4][4];
#pragma unroll
    for (int mt = 0; mt < 2; mt++)
#pragma unroll
        for (int nt = 0; nt < 4; nt++)
#pragma unroll
            for (int r = 0; r < 4; r++) acc[mt][nt][r] = 0.f;

    const int NCH = K >> 5;
    uint4 vah, val, vbh, vbl;

    // prologue: load chunk0 -> stage0; preload chunk1
    vah = *(const uint4*)pAh;  val = *(const uint4*)pAl;
    vbh = *(const uint4*)pBh;  vbl = *(const uint4*)pBl;
    {
        char* st = smraw;
        *(uint4*)(st + stsoff)             = vah;
        *(uint4*)(st + BLK_B + stsoff)     = val;
        *(uint4*)(st + 2 * BLK_B + stsoff) = vbh;
        *(uint4*)(st + 3 * BLK_B + stsoff) = vbl;
    }
    if (NCH > 1) {
        vah = *(const uint4*)(pAh + 32);  val = *(const uint4*)(pAl + 32);
        vbh = *(const uint4*)(pBh + 32);  vbl = *(const uint4*)(pBl + 32);
    }
    __syncthreads();

    for (int ch = 0; ch < NCH; ch++) {
        if (ch + 1 < NCH) {
            char* st = smraw + ((ch + 1) & 1) * STG_B;
            *(uint4*)(st + stsoff)             = vah;
            *(uint4*)(st + BLK_B + stsoff)     = val;
            *(uint4*)(st + 2 * BLK_B + stsoff) = vbh;
            *(uint4*)(st + 3 * BLK_B + stsoff) = vbl;
            if (ch + 2 < NCH) {
                int o = (ch + 2) * 32;
                vah = *(const uint4*)(pAh + o);  val = *(const uint4*)(pAl + o);
                vbh = *(const uint4*)(pBh + o);  vbl = *(const uint4*)(pBl + o);
            }
        }

        const uint32_t base = smb + (ch & 1) * STG_B;
#pragma unroll
        for (int kf = 0; kf < 2; kf++) {
            const uint32_t kfB = kf * 32;
            uint32_t ah[2][4], al[2][4], bh[4][2], bl[4][2];
            ldsm4(ah[0][0], ah[0][1], ah[0][2], ah[0][3], base + a_l + kfB);
            ldsm4(ah[1][0], ah[1][1], ah[1][2], ah[1][3], base + a_l + 1280 + kfB);
            ldsm4(al[0][0], al[0][1], al[0][2], al[0][3], base + BLK_B + a_l + kfB);
            ldsm4(al[1][0], al[1][1], al[1][2], al[1][3], base + BLK_B + a_l + 1280 + kfB);
            ldsm4(bh[0][0], bh[0][1], bh[1][0], bh[1][1], base + 2 * BLK_B + b_l + kfB);
            ldsm4(bh[2][0], bh[2][1], bh[3][0], bh[3][1], base + 2 * BLK_B + b_l + 1280 + kfB);
            ldsm4(bl[0][0], bl[0][1], bl[1][0], bl[1][1], base + 3 * BLK_B + b_l + kfB);
            ldsm4(bl[2][0], bl[2][1], bl[3][0], bl[3][1], base + 3 * BLK_B + b_l + 1280 + kfB);
#pragma unroll
            for (int mt = 0; mt < 2; mt++)
#pragma unroll
                for (int nt = 0; nt < 4; nt++) {
                    mma_bf16(acc[mt][nt], ah[mt][0], ah[mt][1], ah[mt][2], ah[mt][3],
                             bh[nt][0], bh[nt][1]);
                    mma_bf16(acc[mt][nt], ah[mt][0], ah[mt][1], ah[mt][2], ah[mt][3],
                             bl[nt][0], bl[nt][1]);
                    mma_bf16(acc[mt][nt], al[mt][0], al[mt][1], al[mt][2], al[mt][3],
                             bh[nt][0], bh[nt][1]);
                }
        }
        __syncthreads();
    }

    // epilogue
#pragma unroll
    for (int mt = 0; mt < 2; mt++) {
#pragma unroll
        for (int nt = 0; nt < 4; nt++) {
            int row0 = bm + wm * 32 + mt * 16 + lr;
            int row1 = row0 + 8;
            int col  = bn + wn * 32 + nt * 8 + lc;
            if (FLIPC) { row0 = flip_row(row0); row1 = flip_row(row1); }
            float2 v0 = make_float2(acc[mt][nt][0], acc[mt][nt][1]);
            float2 v1 = make_float2(acc[mt][nt][2], acc[mt][nt][3]);
            if (bias) {
                float b0 = bias[col], b1 = bias[col + 1];
                v0.x += b0; v0.y += b1; v1.x += b0; v1.y += b1;
            }
            if (EPI == 1) {
                v0.x = 0.5f * v0.x * (1.f + erff(v0.x * 0.70710678118654752f));
                v0.y = 0.5f * v0.y * (1.f + erff(v0.y * 0.70710678118654752f));
                v1.x = 0.5f * v1.x * (1.f + erff(v1.x * 0.70710678118654752f));
                v1.y = 0.5f * v1.y * (1.f + erff(v1.y * 0.70710678118654752f));
            }
            float* p0 = C + (size_t)row0 * ldc + col;
            float* p1 = C + (size_t)row1 * ldc + col;
            if (ACC) {
                float2 o0 = *(float2*)p0, o1 = *(float2*)p1;
                v0.x += o0.x; v0.y += o0.y; v1.x += o1.x; v1.y += o1.y;
            }
            *(float2*)p0 = v0;
            *(float2*)p1 = v1;
        }
    }
}

// -------------------- fp32 SGEMM (small shapes: xproj, dt) ----------------
// EPI: 0=none 2=softplus
template<int EPI>
__global__ void __launch_bounds__(256) gemm_k(
    const float* __restrict__ A, int lda,
    const float* __restrict__ W, int ldb,
    const float* __restrict__ bias,
    float* __restrict__ C, int ldc,
    int N, int K)
{
    __shared__ float As[8][128];
    __shared__ float Bs[8][128];

    const int tid = threadIdx.x;
    const int bm  = blockIdx.y * 128;
    const int bn  = blockIdx.x * 128;
    const int tr  = tid >> 4;
    const int tc  = tid & 15;

    float acc[8][8];
#pragma unroll
    for (int i = 0; i < 8; i++)
#pragma unroll
        for (int j = 0; j < 8; j++) acc[i][j] = 0.f;

    const int lr = tid >> 1;
    const int lk = (tid & 1) * 4;

    const float* Aptr = A + (size_t)(bm + lr) * lda + lk;
    int wn = bn + lr;
    bool wvalid = (wn < N);
    const float* Wptr = wvalid ? (W + (size_t)wn * ldb + lk) : W;

    for (int k0 = 0; k0 < K; k0 += 8) {
        float4 av = *(const float4*)(Aptr + k0);
        float4 wv = wvalid ? *(const float4*)(Wptr + k0) : make_float4(0.f, 0.f, 0.f, 0.f);
        __syncthreads();
        As[lk+0][lr] = av.x; As[lk+1][lr] = av.y; As[lk+2][lr] = av.z; As[lk+3][lr] = av.w;
        Bs[lk+0][lr] = wv.x; Bs[lk+1][lr] = wv.y; Bs[lk+2][lr] = wv.z; Bs[lk+3][lr] = wv.w;
        __syncthreads();
#pragma unroll
        for (int k = 0; k < 8; k++) {
            float ar[8], br[8];
#pragma unroll
            for (int i = 0; i < 8; i++) ar[i] = As[k][tr*8 + i];
#pragma unroll
            for (int j = 0; j < 8; j++) br[j] = Bs[k][tc*8 + j];
#pragma unroll
            for (int i = 0; i < 8; i++)
#pragma unroll
                for (int j = 0; j < 8; j++)
                    acc[i][j] = fmaf(ar[i], br[j], acc[i][j]);
        }
    }

#pragma unroll
    for (int i = 0; i < 8; i++) {
        float* crow = C + (size_t)(bm + tr*8 + i) * ldc;
#pragma unroll
        for (int j = 0; j < 8; j++) {
            int cn = bn + tc*8 + j;
            if (cn < N) {
                float v = acc[i][j];
                if (bias) v += bias[cn];
                if (EPI == 2) v = (v > 20.f) ? v : log1pf(expf(v));
                crow[cn] = v;
            }
        }
    }
}

// -------------------- causal depthwise conv (K=2) + SiLU ------------------
__global__ void conv_silu_k(const float* __restrict__ cw, const float* __restrict__ cb) {
    int i = blockIdx.x * blockDim.x + threadIdx.x;
    if (i >= M_ROWS * D_MODEL) return;
    int d   = i & (D_MODEL - 1);
    int row = i >> 9;
    int l   = row & (SEQ - 1);
    float xi   = g_XZ[(size_t)row * 1024 + d];
    float xim1 = (l > 0) ? g_XZ[(size_t)(row - 1) * 1024 + d] : 0.f;
    float v = cw[d*2 + 0] * xim1 + cw[d*2 + 1] * xi + cb[d];
    g_XC[i] = silu_f(v);
}

// -------------------- selective scan --------------------------------------
__global__ void scan_k(const float* __restrict__ A_log, const float* __restrict__ D_skip) {
    int t = blockIdx.x * blockDim.x + threadIdx.x;
    int n = t & 15;
    int g = t >> 4;
    int b = g >> 9;
    int d = g & (D_MODEL - 1);

    float Aa  = -expf(A_log[d * D_STATE + n]);
    float Dsk = D_skip[d];
    float h = 0.f;
    size_t rbase = (size_t)b * SEQ;

    for (int l = 0; l < SEQ; l++) {
        size_t row = rbase + l;
        float dtv = g_DT[row * D_MODEL + d];
        float xcv = g_XC[row * D_MODEL + d];
        float Bv  = g_PROJ[row * 64 + 32 + n];
        float Cv  = g_PROJ[row * 64 + 48 + n];
        h = expf(dtv * Aa) * h + dtv * Bv * xcv;
        float p = h * Cv;
        p += __shfl_xor_sync(0xffffffffu, p, 8, 16);
        p += __shfl_xor_sync(0xffffffffu, p, 4, 16);
        p += __shfl_xor_sync(0xffffffffu, p, 2, 16);
        p += __shfl_xor_sync(0xffffffffu, p, 1, 16);
        if (n == 0) {
            float z = g_XZ[row * 1024 + 512 + d];
            float y = p + Dsk * xcv;
            g_Y[row * D_MODEL + d] = y * silu_f(z);
        }
    }
}

// -------------------- layernorm (optional residual add) -------------------
__global__ void ln_k(const float* __restrict__ in, const float* __restrict__ res,
                     const float* __restrict__ w, const float* __restrict__ b,
                     float* __restrict__ out)
{
    int row = blockIdx.x;
    int tid = threadIdx.x;
    float v[4];
    float s = 0.f, q = 0.f;
#pragma unroll
    for (int i = 0; i < 4; i++) {
        int c = tid + i * 128;
        float x = in[(size_t)row * D_MODEL + c];
        if (res) x += res[(size_t)row * D_MODEL + c];
        v[i] = x;
        s += x; q += x * x;
    }
    __shared__ float shs[4], shq[4];
#pragma unroll
    for (int off = 16; off; off >>= 1) {
        s += __shfl_xor_sync(0xffffffffu, s, off);
        q += __shfl_xor_sync(0xffffffffu, q, off);
    }
    if ((tid & 31) == 0) { shs[tid >> 5] = s; shq[tid >> 5] = q; }
    __syncthreads();
    if (tid == 0) {
        shs[0] = shs[0] + shs[1] + shs[2] + shs[3];
        shq[0] = shq[0] + shq[1] + shq[2] + shq[3];
    }
    __syncthreads();
    float m   = shs[0] * (1.f / D_MODEL);
    float var = shq[0] * (1.f / D_MODEL) - m * m;
    float inv = rsqrtf(var + 1e-5f);
#pragma unroll
    for (int i = 0; i < 4; i++) {
        int c = tid + i * 128;
        out[(size_t)row * D_MODEL + c] = (v[i] - m) * inv * w[c] + b[c];
    }
}

// ==========================================================================
extern "C" void kernel_launch(void* const* d_in, const int* in_sizes, int n_in,
                              void* d_out, int out_size)
{
    const float* x_in    = (const float*)d_in[0];
    const float* in_w    = (const float*)d_in[1];
    const float* conv_w  = (const float*)d_in[2];
    const float* conv_b  = (const float*)d_in[3];
    const float* xproj_w = (const float*)d_in[4];
    const float* dt_w    = (const float*)d_in[5];
    const float* dt_b    = (const float*)d_in[6];
    const float* A_log   = (const float*)d_in[7];
    const float* D_skip  = (const float*)d_in[8];
    const float* out_w   = (const float*)d_in[9];
    const float* ffn1_w  = (const float*)d_in[10];
    const float* ffn1_b  = (const float*)d_in[11];
    const float* ffn2_w  = (const float*)d_in[12];
    const float* ffn2_b  = (const float*)d_in[13];
    const float* n1_w    = (const float*)d_in[14];
    const float* n1_b    = (const float*)d_in[15];
    const float* n2_w    = (const float*)d_in[16];
    const float* n2_b    = (const float*)d_in[17];
    const float* fn_w    = (const float*)d_in[18];
    const float* fn_b    = (const float*)d_in[19];

    float *X, *XACC, *XZ, *XC, *PROJ, *DT, *Y, *FFNH, *FFNO;
    __nv_bfloat16 *Xhi, *Xlo, *Ahi, *Alo, *Whi, *Wlo;
    cudaGetSymbolAddress((void**)&X,    g_X);
    cudaGetSymbolAddress((void**)&XACC, g_XACC);
    cudaGetSymbolAddress((void**)&XZ,   g_XZ);
    cudaGetSymbolAddress((void**)&XC,   g_XC);
    cudaGetSymbolAddress((void**)&PROJ, g_PROJ);
    cudaGetSymbolAddress((void**)&DT,   g_DT);
    cudaGetSymbolAddress((void**)&Y,    g_Y);
    cudaGetSymbolAddress((void**)&FFNH, g_FFNH);
    cudaGetSymbolAddress((void**)&FFNO, g_FFNO);
    cudaGetSymbolAddress((void**)&Xhi,  g_Xhi);
    cudaGetSymbolAddress((void**)&Xlo,  g_Xlo);
    cudaGetSymbolAddress((void**)&Ahi,  g_Ahi);
    cudaGetSymbolAddress((void**)&Alo,  g_Alo);
    cudaGetSymbolAddress((void**)&Whi,  g_Whi);
    cudaGetSymbolAddress((void**)&Wlo,  g_Wlo);

    cudaFuncSetAttribute(mmagemm_k<0,false,false,false>, cudaFuncAttributeMaxDynamicSharedMemorySize, GEMM_SMEM);
    cudaFuncSetAttribute(mmagemm_k<0,false,true ,false>, cudaFuncAttributeMaxDynamicSharedMemorySize, GEMM_SMEM);
    cudaFuncSetAttribute(mmagemm_k<0,true ,false,false>, cudaFuncAttributeMaxDynamicSharedMemorySize, GEMM_SMEM);
    cudaFuncSetAttribute(mmagemm_k<0,true ,false,true >, cudaFuncAttributeMaxDynamicSharedMemorySize, GEMM_SMEM);
    cudaFuncSetAttribute(mmagemm_k<1,false,false,false>, cudaFuncAttributeMaxDynamicSharedMemorySize, GEMM_SMEM);

    const int NELEM = M_ROWS * D_MODEL;   // 4194304
    const int cgrid = (NELEM + 255) / 256;
    auto SPLIT = [&](const float* src, __nv_bfloat16* hi, __nv_bfloat16* lo, int n) {
        split_bf16_k<<<(n / 4 + 255) / 256, 256>>>(src, hi, lo, n);
    };

    copy_k<<<cgrid, 256>>>(X, x_in, NELEM);

    for (int e = 0; e < E_LAYERS; e++) {
        copy_k<<<cgrid, 256>>>(XACC, X, NELEM);
        SPLIT(X, Xhi, Xlo, NELEM);

        for (int dir = 0; dir < 2; dir++) {
            int s = e * 2 + dir;
            const float* inw  = in_w    + (size_t)s * 1024 * 512;
            const float* cw   = conv_w  + (size_t)s * 512 * 2;
            const float* cb   = conv_b  + (size_t)s * 512;
            const float* xpw  = xproj_w + (size_t)s * 64 * 512;
            const float* dtw  = dt_w    + (size_t)s * 512 * 32;
            const float* dtb  = dt_b    + (size_t)s * 512;
            const float* alog = A_log   + (size_t)s * 512 * 16;
            const float* dsk  = D_skip  + (size_t)s * 512;
            const float* ow   = out_w   + (size_t)s * 512 * 512;

            // 1) xz = x @ in_w^T
            SPLIT(inw, Whi, Wlo, 1024 * 512);
            {
                dim3 g(1024 / BN, M_ROWS / BM);
                if (dir == 0)
                    mmagemm_k<0,false,false,false><<<g,512,GEMM_SMEM>>>(Xhi,Xlo,Whi,Wlo,nullptr,XZ,1024,512);
                else
                    mmagemm_k<0,false,true ,false><<<g,512,GEMM_SMEM>>>(Xhi,Xlo,Whi,Wlo,nullptr,XZ,1024,512);
            }
            // 2) conv + silu
            conv_silu_k<<<cgrid, 256>>>(cw, cb);
            // 3) proj = xc @ xproj^T (N=64, fp32 path)
            {
                dim3 g(1, M_ROWS / 128);
                gemm_k<0><<<g,256>>>(XC,512, xpw,512, nullptr, PROJ,64, 64,512);
            }
            // 4) dt = softplus(proj[:, :32] @ dt_w^T + dt_b)
            {
                dim3 g(512 / 128, M_ROWS / 128);
                gemm_k<2><<<g,256>>>(PROJ,64, dtw,32, dtb, DT,512, 512,32);
            }
            // 5) selective scan -> Y
            scan_k<<<(M_ROWS * 16) / 256, 256>>>(alog, dsk);
            // 6) XACC += Y @ out_w^T
            SPLIT(Y, Ahi, Alo, NELEM);
            SPLIT(ow, Whi, Wlo, 512 * 512);
            {
                dim3 g(512 / BN, M_ROWS / BM);
                if (dir == 0)
                    mmagemm_k<0,true,false,false><<<g,512,GEMM_SMEM>>>(Ahi,Alo,Whi,Wlo,nullptr,XACC,512,512);
                else
                    mmagemm_k<0,true,false,true ><<<g,512,GEMM_SMEM>>>(Ahi,Alo,Whi,Wlo,nullptr,XACC,512,512);
            }
        }

        // LN1
        ln_k<<<M_ROWS, 128>>>(XACC, nullptr, n1_w + e*512, n1_b + e*512, X);

        // FFN1: h = gelu(x @ W1^T + b1)
        SPLIT(X, Xhi, Xlo, NELEM);
        SPLIT(ffn1_w + (size_t)e * D_FF * 512, Whi, Wlo, D_FF * 512);
        {
            dim3 g(D_FF / BN, M_ROWS / BM);
            mmagemm_k<1,false,false,false><<<g,512,GEMM_SMEM>>>(Xhi,Xlo,Whi,Wlo,ffn1_b + e*D_FF,FFNH,D_FF,512);
        }
        // FFN2: y = h @ W2^T + b2
        SPLIT(FFNH, Ahi, Alo, M_ROWS * D_FF);
        SPLIT(ffn2_w + (size_t)e * 512 * D_FF, Whi, Wlo, 512 * D_FF);
        {
            dim3 g(512 / BN, M_ROWS / BM);
            mmagemm_k<0,false,false,false><<<g,512,GEMM_SMEM>>>(Ahi,Alo,Whi,Wlo,ffn2_b + e*512,FFNO,512,2048);
        }
        // LN2
        ln_k<<<M_ROWS, 128>>>(X, FFNO, n2_w + e*512, n2_b + e*512, X);
    }

    ln_k<<<M_ROWS, 128>>>(X, nullptr, fn_w, fn_b, (float*)d_out);
}

// round 17
// speedup vs baseline: 1.7007x; 1.0984x over previous
#include <cuda_runtime.h>
#include <cuda_bf16.h>
#include <math.h>
#include <stdint.h>

// Problem constants
#define E_LAYERS 2
#define D_MODEL  512
#define D_STATE  16
#define DT_RANK  32
#define D_FF     2048
#define BATCH    16
#define SEQ      512
#define M_ROWS   (BATCH*SEQ)   // 8192

// -------------------- scratch (device globals; no allocation allowed) -----
__device__ float g_X   [M_ROWS * D_MODEL];
__device__ float g_XACC[M_ROWS * D_MODEL];
__device__ float g_XZ  [M_ROWS * 2 * D_MODEL];
__device__ float g_XC  [M_ROWS * D_MODEL];
__device__ float g_PROJ[M_ROWS * 64];
__device__ float g_DT  [M_ROWS * D_MODEL];
__device__ float g_FFNO[M_ROWS * D_MODEL];
// bf16 hi/lo split operand buffers
__device__ __nv_bfloat16 g_Xhi[M_ROWS * D_MODEL];
__device__ __nv_bfloat16 g_Xlo[M_ROWS * D_MODEL];
__device__ __nv_bfloat16 g_Ahi[M_ROWS * D_FF];   // scan-Y / FFN hidden hi
__device__ __nv_bfloat16 g_Alo[M_ROWS * D_FF];   // scan-Y / FFN hidden lo
__device__ __nv_bfloat16 g_Whi[D_FF * D_MODEL];
__device__ __nv_bfloat16 g_Wlo[D_FF * D_MODEL];

__device__ __forceinline__ int flip_row(int m) {
    return (m & ~(SEQ - 1)) + (SEQ - 1 - (m & (SEQ - 1)));
}

__device__ __forceinline__ void cvt_hl(float x, float y,
                                       __nv_bfloat162& h2, __nv_bfloat162& l2) {
    h2 = __floats2bfloat162_rn(x, y);
    l2 = __floats2bfloat162_rn(x - __bfloat162float(h2.x),
                               y - __bfloat162float(h2.y));
}

// -------------------- copy + optional hi/lo split --------------------------
__global__ void copy_split_k(float* __restrict__ dst, const float* __restrict__ src,
                             __nv_bfloat16* __restrict__ hi,
                             __nv_bfloat16* __restrict__ lo, int n) {
    int i = (blockIdx.x * blockDim.x + threadIdx.x) * 4;
    if (i >= n) return;
    float4 v = *(const float4*)(src + i);
    *(float4*)(dst + i) = v;
    __nv_bfloat162 h0, l0, h1, l1;
    cvt_hl(v.x, v.y, h0, l0);
    cvt_hl(v.z, v.w, h1, l1);
    *(__nv_bfloat162*)(hi + i)     = h0;
    *(__nv_bfloat162*)(hi + i + 2) = h1;
    *(__nv_bfloat162*)(lo + i)     = l0;
    *(__nv_bfloat162*)(lo + i + 2) = l1;
}

__global__ void copy_k(float* __restrict__ dst, const float* __restrict__ src, int n) {
    int i = blockIdx.x * blockDim.x + threadIdx.x;
    if (i < n) dst[i] = src[i];
}

// -------------------- fp32 -> bf16 hi/lo split (weights) -------------------
__global__ void split_bf16_k(const float* __restrict__ src,
                             __nv_bfloat16* __restrict__ hi,
                             __nv_bfloat16* __restrict__ lo, int n) {
    int i = (blockIdx.x * blockDim.x + threadIdx.x) * 4;
    if (i >= n) return;
    float4 v = *(const float4*)(src + i);
    __nv_bfloat162 h0, l0, h1, l1;
    cvt_hl(v.x, v.y, h0, l0);
    cvt_hl(v.z, v.w, h1, l1);
    *(__nv_bfloat162*)(hi + i)     = h0;
    *(__nv_bfloat162*)(hi + i + 2) = h1;
    *(__nv_bfloat162*)(lo + i)     = l0;
    *(__nv_bfloat162*)(lo + i + 2) = l1;
}

// ==================== bf16x3 tensor-core GEMM (mma.sync + ldmatrix) =======
// C[m,n] = sum_k A[m,k]*W[n,k]. Operands pre-split into bf16 hi/lo arrays.
// Emulated fp32: Ah*Bh + Ah*Bl + Al*Bh (fp32 accum).
// CTA tile 128x128, BK=32, 512 threads, 16 warps (4x4), warp tile 32x32.
// EPI: 0=none 1=gelu. ACC: C+=. FLIPA/FLIPC: seq-flip. OUTHL: emit bf16 hi/lo.
#define BM   128
#define BN   128
#define PADK 40
#define BLK_B  (128 * PADK * 2)          // 10240 B
#define STG_B  (4 * BLK_B)               // 40960 B
#define GEMM_SMEM (2 * STG_B)            // 81920 B

__device__ __forceinline__ void mma_bf16(float c[4], uint32_t a0, uint32_t a1,
                                         uint32_t a2, uint32_t a3,
                                         uint32_t b0, uint32_t b1) {
    asm volatile(
        "mma.sync.aligned.m16n8k16.row.col.f32.bf16.bf16.f32 "
        "{%0,%1,%2,%3}, {%4,%5,%6,%7}, {%8,%9}, {%0,%1,%2,%3};"
        : "+f"(c[0]), "+f"(c[1]), "+f"(c[2]), "+f"(c[3])
        : "r"(a0), "r"(a1), "r"(a2), "r"(a3), "r"(b0), "r"(b1));
}

__device__ __forceinline__ void ldsm4(uint32_t& r0, uint32_t& r1,
                                      uint32_t& r2, uint32_t& r3, uint32_t addr) {
    asm volatile("ldmatrix.sync.aligned.m8n8.x4.shared.b16 {%0,%1,%2,%3}, [%4];"
                 : "=r"(r0), "=r"(r1), "=r"(r2), "=r"(r3) : "r"(addr));
}

template<int EPI, bool ACC, bool FLIPA, bool FLIPC, bool OUTHL>
__global__ void __launch_bounds__(512, 1) mmagemm_k(
    const __nv_bfloat16* __restrict__ Ahi, const __nv_bfloat16* __restrict__ Alo,
    const __nv_bfloat16* __restrict__ Whi, const __nv_bfloat16* __restrict__ Wlo,
    const float* __restrict__ bias,
    float* __restrict__ C,
    __nv_bfloat16* __restrict__ OutHi, __nv_bfloat16* __restrict__ OutLo,
    int ldc, int K)
{
    extern __shared__ char smraw[];

    const int tid  = threadIdx.x;
    const int lane = tid & 31;
    const int warp = tid >> 5;
    const int wm   = warp >> 2;
    const int wn   = warp & 3;
    const int lr   = lane >> 2;
    const int lc   = (lane & 3) * 2;
    const int bm   = blockIdx.y * BM;
    const int bn   = blockIdx.x * BN;

    const int l_row = tid >> 2;
    const int l_k0  = (tid & 3) * 8;

    int arow = bm + l_row;
    if (FLIPA) arow = flip_row(arow);
    const __nv_bfloat16* pAh = Ahi + (size_t)arow * K + l_k0;
    const __nv_bfloat16* pAl = Alo + (size_t)arow * K + l_k0;
    const __nv_bfloat16* pBh = Whi + (size_t)(bn + l_row) * K + l_k0;
    const __nv_bfloat16* pBl = Wlo + (size_t)(bn + l_row) * K + l_k0;

    const uint32_t smb    = (uint32_t)__cvta_generic_to_shared(smraw);
    const uint32_t stsoff = (uint32_t)(l_row * 80 + l_k0 * 2);
    const uint32_t a_l = (uint32_t)((wm * 32 + (lane & 15)) * 80 + ((lane >> 4) & 1) * 16);
    const uint32_t b_l = (uint32_t)((wn * 32 + (lane & 7) + ((lane >> 4) & 1) * 8) * 80
                                    + ((lane >> 3) & 1) * 16);

    float acc[2][4][4];
#pragma unroll
    for (int mt = 0; mt < 2; mt++)
#pragma unroll
        for (int nt = 0; nt < 4; nt++)
#pragma unroll
            for (int r = 0; r < 4; r++) acc[mt][nt][r] = 0.f;

    const int NCH = K >> 5;
    uint4 vah, val, vbh, vbl;

    vah = *(const uint4*)pAh;  val = *(const uint4*)pAl;
    vbh = *(const uint4*)pBh;  vbl = *(const uint4*)pBl;
    {
        char* st = smraw;
        *(uint4*)(st + stsoff)             = vah;
        *(uint4*)(st + BLK_B + stsoff)     = val;
        *(uint4*)(st + 2 * BLK_B + stsoff) = vbh;
        *(uint4*)(st + 3 * BLK_B + stsoff) = vbl;
    }
    if (NCH > 1) {
        vah = *(const uint4*)(pAh + 32);  val = *(const uint4*)(pAl + 32);
        vbh = *(const uint4*)(pBh + 32);  vbl = *(const uint4*)(pBl + 32);
    }
    __syncthreads();

    for (int ch = 0; ch < NCH; ch++) {
        if (ch + 1 < NCH) {
            char* st = smraw + ((ch + 1) & 1) * STG_B;
            *(uint4*)(st + stsoff)             = vah;
            *(uint4*)(st + BLK_B + stsoff)     = val;
            *(uint4*)(st + 2 * BLK_B + stsoff) = vbh;
            *(uint4*)(st + 3 * BLK_B + stsoff) = vbl;
            if (ch + 2 < NCH) {
                int o = (ch + 2) * 32;
                vah = *(const uint4*)(pAh + o);  val = *(const uint4*)(pAl + o);
                vbh = *(const uint4*)(pBh + o);  vbl = *(const uint4*)(pBl + o);
            }
        }

        const uint32_t base = smb + (ch & 1) * STG_B;
#pragma unroll
        for (int kf = 0; kf < 2; kf++) {
            const uint32_t kfB = kf * 32;
            uint32_t ah[2][4], al[2][4], bh[4][2], bl[4][2];
            ldsm4(ah[0][0], ah[0][1], ah[0][2], ah[0][3], base + a_l + kfB);
            ldsm4(ah[1][0], ah[1][1], ah[1][2], ah[1][3], base + a_l + 1280 + kfB);
            ldsm4(al[0][0], al[0][1], al[0][2], al[0][3], base + BLK_B + a_l + kfB);
            ldsm4(al[1][0], al[1][1], al[1][2], al[1][3], base + BLK_B + a_l + 1280 + kfB);
            ldsm4(bh[0][0], bh[0][1], bh[1][0], bh[1][1], base + 2 * BLK_B + b_l + kfB);
            ldsm4(bh[2][0], bh[2][1], bh[3][0], bh[3][1], base + 2 * BLK_B + b_l + 1280 + kfB);
            ldsm4(bl[0][0], bl[0][1], bl[1][0], bl[1][1], base + 3 * BLK_B + b_l + kfB);
            ldsm4(bl[2][0], bl[2][1], bl[3][0], bl[3][1], base + 3 * BLK_B + b_l + 1280 + kfB);
#pragma unroll
            for (int mt = 0; mt < 2; mt++)
#pragma unroll
                for (int nt = 0; nt < 4; nt++) {
                    mma_bf16(acc[mt][nt], ah[mt][0], ah[mt][1], ah[mt][2], ah[mt][3],
                             bh[nt][0], bh[nt][1]);
                    mma_bf16(acc[mt][nt], ah[mt][0], ah[mt][1], ah[mt][2], ah[mt][3],
                             bl[nt][0], bl[nt][1]);
                    mma_bf16(acc[mt][nt], al[mt][0], al[mt][1], al[mt][2], al[mt][3],
                             bh[nt][0], bh[nt][1]);
                }
        }
        __syncthreads();
    }

    // epilogue
#pragma unroll
    for (int mt = 0; mt < 2; mt++) {
#pragma unroll
        for (int nt = 0; nt < 4; nt++) {
            int row0 = bm + wm * 32 + mt * 16 + lr;
            int row1 = row0 + 8;
            int col  = bn + wn * 32 + nt * 8 + lc;
            if (FLIPC) { row0 = flip_row(row0); row1 = flip_row(row1); }
            float2 v0 = make_float2(acc[mt][nt][0], acc[mt][nt][1]);
            float2 v1 = make_float2(acc[mt][nt][2], acc[mt][nt][3]);
            if (bias) {
                float b0 = bias[col], b1 = bias[col + 1];
                v0.x += b0; v0.y += b1; v1.x += b0; v1.y += b1;
            }
            if (EPI == 1) {
                v0.x = 0.5f * v0.x * (1.f + erff(v0.x * 0.70710678118654752f));
                v0.y = 0.5f * v0.y * (1.f + erff(v0.y * 0.70710678118654752f));
                v1.x = 0.5f * v1.x * (1.f + erff(v1.x * 0.70710678118654752f));
                v1.y = 0.5f * v1.y * (1.f + erff(v1.y * 0.70710678118654752f));
            }
            if (OUTHL) {
                __nv_bfloat162 h2, l2;
                cvt_hl(v0.x, v0.y, h2, l2);
                *(__nv_bfloat162*)&OutHi[(size_t)row0 * ldc + col] = h2;
                *(__nv_bfloat162*)&OutLo[(size_t)row0 * ldc + col] = l2;
                cvt_hl(v1.x, v1.y, h2, l2);
                *(__nv_bfloat162*)&OutHi[(size_t)row1 * ldc + col] = h2;
                *(__nv_bfloat162*)&OutLo[(size_t)row1 * ldc + col] = l2;
            } else {
                float* p0 = C + (size_t)row0 * ldc + col;
                float* p1 = C + (size_t)row1 * ldc + col;
                if (ACC) {
                    float2 o0 = *(float2*)p0, o1 = *(float2*)p1;
                    v0.x += o0.x; v0.y += o0.y; v1.x += o1.x; v1.y += o1.y;
                }
                *(float2*)p0 = v0;
                *(float2*)p1 = v1;
            }
        }
    }
}

// -------------------- fp32 SGEMM (small shapes: xproj, dt) ----------------
template<int EPI>
__global__ void __launch_bounds__(256) gemm_k(
    const float* __restrict__ A, int lda,
    const float* __restrict__ W, int ldb,
    const float* __restrict__ bias,
    float* __restrict__ C, int ldc,
    int N, int K)
{
    __shared__ float As[8][128];
    __shared__ float Bs[8][128];

    const int tid = threadIdx.x;
    const int bm  = blockIdx.y * 128;
    const int bn  = blockIdx.x * 128;
    const int tr  = tid >> 4;
    const int tc  = tid & 15;

    float acc[8][8];
#pragma unroll
    for (int i = 0; i < 8; i++)
#pragma unroll
        for (int j = 0; j < 8; j++) acc[i][j] = 0.f;

    const int lr = tid >> 1;
    const int lk = (tid & 1) * 4;

    const float* Aptr = A + (size_t)(bm + lr) * lda + lk;
    int wn = bn + lr;
    bool wvalid = (wn < N);
    const float* Wptr = wvalid ? (W + (size_t)wn * ldb + lk) : W;

    for (int k0 = 0; k0 < K; k0 += 8) {
        float4 av = *(const float4*)(Aptr + k0);
        float4 wv = wvalid ? *(const float4*)(Wptr + k0) : make_float4(0.f, 0.f, 0.f, 0.f);
        __syncthreads();
        As[lk+0][lr] = av.x; As[lk+1][lr] = av.y; As[lk+2][lr] = av.z; As[lk+3][lr] = av.w;
        Bs[lk+0][lr] = wv.x; Bs[lk+1][lr] = wv.y; Bs[lk+2][lr] = wv.z; Bs[lk+3][lr] = wv.w;
        __syncthreads();
#pragma unroll
        for (int k = 0; k < 8; k++) {
            float ar[8], br[8];
#pragma unroll
            for (int i = 0; i < 8; i++) ar[i] = As[k][tr*8 + i];
#pragma unroll
            for (int j = 0; j < 8; j++) br[j] = Bs[k][tc*8 + j];
#pragma unroll
            for (int i = 0; i < 8; i++)
#pragma unroll
                for (int j = 0; j < 8; j++)
                    acc[i][j] = fmaf(ar[i], br[j], acc[i][j]);
        }
    }

#pragma unroll
    for (int i = 0; i < 8; i++) {
        float* crow = C + (size_t)(bm + tr*8 + i) * ldc;
#pragma unroll
        for (int j = 0; j < 8; j++) {
            int cn = bn + tc*8 + j;
            if (cn < N) {
                float v = acc[i][j];
                if (bias) v += bias[cn];
                if (EPI == 2) v = (v > 20.f) ? v : log1pf(expf(v));
                crow[cn] = v;
            }
        }
    }
}

// -------------------- causal depthwise conv (K=2) + SiLU ------------------
__global__ void conv_silu_k(const float* __restrict__ cw, const float* __restrict__ cb) {
    int i = blockIdx.x * blockDim.x + threadIdx.x;
    if (i >= M_ROWS * D_MODEL) return;
    int d   = i & (D_MODEL - 1);
    int row = i >> 9;
    int l   = row & (SEQ - 1);
    float xi   = g_XZ[(size_t)row * 1024 + d];
    float xim1 = (l > 0) ? g_XZ[(size_t)(row - 1) * 1024 + d] : 0.f;
    float v = cw[d*2 + 0] * xim1 + cw[d*2 + 1] * xi + cb[d];
    g_XC[i] = v / (1.f + __expf(-v));
}

// -------------------- selective scan (fused bf16 hi/lo output) ------------
__global__ void scan_k(const float* __restrict__ A_log, const float* __restrict__ D_skip,
                       __nv_bfloat16* __restrict__ Yhi, __nv_bfloat16* __restrict__ Ylo) {
    int t = blockIdx.x * blockDim.x + threadIdx.x;
    int n = t & 15;
    int g = t >> 4;
    int b = g >> 9;
    int d = g & (D_MODEL - 1);

    float Aa  = -expf(A_log[d * D_STATE + n]);
    float Dsk = D_skip[d];
    float h = 0.f;

    const float* dtp = g_DT   + (size_t)b * SEQ * D_MODEL + d;
    const float* xcp = g_XC   + (size_t)b * SEQ * D_MODEL + d;
    const float* prp = g_PROJ + (size_t)b * SEQ * 64 + 32 + n;
    const float* zp  = g_XZ   + (size_t)b * SEQ * 1024 + 512 + d;
    size_t ybase = (size_t)b * SEQ * D_MODEL + d;

    for (int l0 = 0; l0 < SEQ; l0 += 4) {
        float dtv[4], xcv[4], Bv[4], Cv[4];
#pragma unroll
        for (int j = 0; j < 4; j++) {
            dtv[j] = dtp[(size_t)(l0 + j) * D_MODEL];
            xcv[j] = xcp[(size_t)(l0 + j) * D_MODEL];
            Bv[j]  = prp[(size_t)(l0 + j) * 64];
            Cv[j]  = prp[(size_t)(l0 + j) * 64 + 16];
        }
#pragma unroll
        for (int j = 0; j < 4; j++) {
            h = __expf(dtv[j] * Aa) * h + dtv[j] * Bv[j] * xcv[j];
            float p = h * Cv[j];
            p += __shfl_xor_sync(0xffffffffu, p, 8, 16);
            p += __shfl_xor_sync(0xffffffffu, p, 4, 16);
            p += __shfl_xor_sync(0xffffffffu, p, 2, 16);
            p += __shfl_xor_sync(0xffffffffu, p, 1, 16);
            if (n == 0) {
                float z = zp[(size_t)(l0 + j) * 1024];
                float y = (p + Dsk * xcv[j]) * (z / (1.f + __expf(-z)));
                __nv_bfloat16 hb = __float2bfloat16(y);
                Yhi[ybase + (size_t)(l0 + j) * D_MODEL] = hb;
                Ylo[ybase + (size_t)(l0 + j) * D_MODEL] =
                    __float2bfloat16(y - __bfloat162float(hb));
            }
        }
    }
}

// -------------------- layernorm (+residual, + optional hi/lo out) ---------
__global__ void ln_k(const float* __restrict__ in, const float* __restrict__ res,
                     const float* __restrict__ w, const float* __restrict__ b,
                     float* __restrict__ out,
                     __nv_bfloat16* __restrict__ ohi, __nv_bfloat16* __restrict__ olo)
{
    int row = blockIdx.x;
    int tid = threadIdx.x;
    float v[4];
    float s = 0.f, q = 0.f;
#pragma unroll
    for (int i = 0; i < 4; i++) {
        int c = tid + i * 128;
        float x = in[(size_t)row * D_MODEL + c];
        if (res) x += res[(size_t)row * D_MODEL + c];
        v[i] = x;
        s += x; q += x * x;
    }
    __shared__ float shs[4], shq[4];
#pragma unroll
    for (int off = 16; off; off >>= 1) {
        s += __shfl_xor_sync(0xffffffffu, s, off);
        q += __shfl_xor_sync(0xffffffffu, q, off);
    }
    if ((tid & 31) == 0) { shs[tid >> 5] = s; shq[tid >> 5] = q; }
    __syncthreads();
    if (tid == 0) {
        shs[0] = shs[0] + shs[1] + shs[2] + shs[3];
        shq[0] = shq[0] + shq[1] + shq[2] + shq[3];
    }
    __syncthreads();
    float m   = shs[0] * (1.f / D_MODEL);
    float var = shq[0] * (1.f / D_MODEL) - m * m;
    float inv = rsqrtf(var + 1e-5f);
#pragma unroll
    for (int i = 0; i < 4; i++) {
        int c = tid + i * 128;
        float o = (v[i] - m) * inv * w[c] + b[c];
        out[(size_t)row * D_MODEL + c] = o;
        if (ohi) {
            __nv_bfloat16 hb = __float2bfloat16(o);
            ohi[(size_t)row * D_MODEL + c] = hb;
            olo[(size_t)row * D_MODEL + c] = __float2bfloat16(o - __bfloat162float(hb));
        }
    }
}

// ==========================================================================
extern "C" void kernel_launch(void* const* d_in, const int* in_sizes, int n_in,
                              void* d_out, int out_size)
{
    const float* x_in    = (const float*)d_in[0];
    const float* in_w    = (const float*)d_in[1];
    const float* conv_w  = (const float*)d_in[2];
    const float* conv_b  = (const float*)d_in[3];
    const float* xproj_w = (const float*)d_in[4];
    const float* dt_w    = (const float*)d_in[5];
    const float* dt_b    = (const float*)d_in[6];
    const float* A_log   = (const float*)d_in[7];
    const float* D_skip  = (const float*)d_in[8];
    const float* out_w   = (const float*)d_in[9];
    const float* ffn1_w  = (const float*)d_in[10];
    const float* ffn1_b  = (const float*)d_in[11];
    const float* ffn2_w  = (const float*)d_in[12];
    const float* ffn2_b  = (const float*)d_in[13];
    const float* n1_w    = (const float*)d_in[14];
    const float* n1_b    = (const float*)d_in[15];
    const float* n2_w    = (const float*)d_in[16];
    const float* n2_b    = (const float*)d_in[17];
    const float* fn_w    = (const float*)d_in[18];
    const float* fn_b    = (const float*)d_in[19];

    float *X, *XACC, *XZ, *XC, *PROJ, *DT, *FFNO;
    __nv_bfloat16 *Xhi, *Xlo, *Ahi, *Alo, *Whi, *Wlo;
    cudaGetSymbolAddress((void**)&X,    g_X);
    cudaGetSymbolAddress((void**)&XACC, g_XACC);
    cudaGetSymbolAddress((void**)&XZ,   g_XZ);
    cudaGetSymbolAddress((void**)&XC,   g_XC);
    cudaGetSymbolAddress((void**)&PROJ, g_PROJ);
    cudaGetSymbolAddress((void**)&DT,   g_DT);
    cudaGetSymbolAddress((void**)&FFNO, g_FFNO);
    cudaGetSymbolAddress((void**)&Xhi,  g_Xhi);
    cudaGetSymbolAddress((void**)&Xlo,  g_Xlo);
    cudaGetSymbolAddress((void**)&Ahi,  g_Ahi);
    cudaGetSymbolAddress((void**)&Alo,  g_Alo);
    cudaGetSymbolAddress((void**)&Whi,  g_Whi);
    cudaGetSymbolAddress((void**)&Wlo,  g_Wlo);

    cudaFuncSetAttribute(mmagemm_k<0,false,false,false,false>, cudaFuncAttributeMaxDynamicSharedMemorySize, GEMM_SMEM);
    cudaFuncSetAttribute(mmagemm_k<0,false,true ,false,false>, cudaFuncAttributeMaxDynamicSharedMemorySize, GEMM_SMEM);
    cudaFuncSetAttribute(mmagemm_k<0,true ,false,false,false>, cudaFuncAttributeMaxDynamicSharedMemorySize, GEMM_SMEM);
    cudaFuncSetAttribute(mmagemm_k<0,true ,false,true ,false>, cudaFuncAttributeMaxDynamicSharedMemorySize, GEMM_SMEM);
    cudaFuncSetAttribute(mmagemm_k<1,false,false,false,true >, cudaFuncAttributeMaxDynamicSharedMemorySize, GEMM_SMEM);

    const int NELEM = M_ROWS * D_MODEL;   // 4194304
    const int cgrid = (NELEM + 255) / 256;
    auto SPLIT = [&](const float* src, __nv_bfloat16* hi, __nv_bfloat16* lo, int n) {
        split_bf16_k<<<(n / 4 + 255) / 256, 256>>>(src, hi, lo, n);
    };

    // X = x_in (fp32 + hi/lo)
    copy_split_k<<<(NELEM / 4 + 255) / 256, 256>>>(X, x_in, Xhi, Xlo, NELEM);

    for (int e = 0; e < E_LAYERS; e++) {
        copy_k<<<cgrid, 256>>>(XACC, X, NELEM);

        for (int dir = 0; dir < 2; dir++) {
            int s = e * 2 + dir;
            const float* inw  = in_w    + (size_t)s * 1024 * 512;
            const float* cw   = conv_w  + (size_t)s * 512 * 2;
            const float* cb   = conv_b  + (size_t)s * 512;
            const float* xpw  = xproj_w + (size_t)s * 64 * 512;
            const float* dtw  = dt_w    + (size_t)s * 512 * 32;
            const float* dtb  = dt_b    + (size_t)s * 512;
            const float* alog = A_log   + (size_t)s * 512 * 16;
            const float* dsk  = D_skip  + (size_t)s * 512;
            const float* ow   = out_w   + (size_t)s * 512 * 512;

            // 1) xz = x @ in_w^T
            SPLIT(inw, Whi, Wlo, 1024 * 512);
            {
                dim3 g(1024 / BN, M_ROWS / BM);
                if (dir == 0)
                    mmagemm_k<0,false,false,false,false><<<g,512,GEMM_SMEM>>>(
                        Xhi,Xlo,Whi,Wlo,nullptr,XZ,nullptr,nullptr,1024,512);
                else
                    mmagemm_k<0,false,true ,false,false><<<g,512,GEMM_SMEM>>>(
                        Xhi,Xlo,Whi,Wlo,nullptr,XZ,nullptr,nullptr,1024,512);
            }
            // 2) conv + silu
            conv_silu_k<<<cgrid, 256>>>(cw, cb);
            // 3) proj = xc @ xproj^T
            {
                dim3 g(1, M_ROWS / 128);
                gemm_k<0><<<g,256>>>(XC,512, xpw,512, nullptr, PROJ,64, 64,512);
            }
            // 4) dt = softplus(proj[:, :32] @ dt_w^T + dt_b)
            {
                dim3 g(512 / 128, M_ROWS / 128);
                gemm_k<2><<<g,256>>>(PROJ,64, dtw,32, dtb, DT,512, 512,32);
            }
            // 5) selective scan -> Y (bf16 hi/lo in Ahi/Alo)
            scan_k<<<(M_ROWS * 16) / 256, 256>>>(alog, dsk, Ahi, Alo);
            // 6) XACC += Y @ out_w^T
            SPLIT(ow, Whi, Wlo, 512 * 512);
            {
                dim3 g(512 / BN, M_ROWS / BM);
                if (dir == 0)
                    mmagemm_k<0,true,false,false,false><<<g,512,GEMM_SMEM>>>(
                        Ahi,Alo,Whi,Wlo,nullptr,XACC,nullptr,nullptr,512,512);
                else
                    mmagemm_k<0,true,false,true ,false><<<g,512,GEMM_SMEM>>>(
                        Ahi,Alo,Whi,Wlo,nullptr,XACC,nullptr,nullptr,512,512);
            }
        }

        // LN1 -> X fp32 + Xhi/Xlo
        ln_k<<<M_ROWS, 128>>>(XACC, nullptr, n1_w + e*512, n1_b + e*512, X, Xhi, Xlo);

        // FFN1: h = gelu(x @ W1^T + b1) -> bf16 hi/lo (Ahi/Alo)
        SPLIT(ffn1_w + (size_t)e * D_FF * 512, Whi, Wlo, D_FF * 512);
        {
            dim3 g(D_FF / BN, M_ROWS / BM);
            mmagemm_k<1,false,false,false,true><<<g,512,GEMM_SMEM>>>(
                Xhi,Xlo,Whi,Wlo,ffn1_b + e*D_FF,nullptr,Ahi,Alo,D_FF,512);
        }
        // FFN2: y = h @ W2^T + b2
        SPLIT(ffn2_w + (size_t)e * 512 * D_FF, Whi, Wlo, 512 * D_FF);
        {
            dim3 g(512 / BN, M_ROWS / BM);
            mmagemm_k<0,false,false,false,false><<<g,512,GEMM_SMEM>>>(
                Ahi,Alo,Whi,Wlo,ffn2_b + e*512,FFNO,nullptr,nullptr,512,2048);
        }
        // LN2 -> X fp32 + Xhi/Xlo (next layer's in-proj input)
        ln_k<<<M_ROWS, 128>>>(X, FFNO, n2_w + e*512, n2_b + e*512, X, Xhi, Xlo);
    }

    // final LN -> d_out
    ln_k<<<M_ROWS, 128>>>(X, nullptr, fn_w, fn_b, (float*)d_out, nullptr, nullptr);
}